// round 11
// baseline (speedup 1.0000x reference)
#include <cuda_runtime.h>
#include <cuda_fp16.h>
#include <math.h>
#include <stdint.h>

// ---------------- problem constants ----------------
#define B_ 2
#define T_ 4096
#define HID_ 2048
#define H_ 6
#define DKH 256
#define DVH 512
#define KEYD 1536
#define VALD 3072
#define ROWS_ (B_ * T_)          // 8192
#define DVS 64                   // dv slice per scan CTA
#define NSL 8                    // 512/64
#define TOKB 8                   // tokens staged per scan round
#define LOSCALE 2048.0f
#define INVLOSCALE (1.0f / 2048.0f)
#define SCAN_CTAS (B_ * H_ * NSL)   // 96

// ---------------- scratch (device globals; no allocation allowed) ----------------
__device__ float g_xq[ROWS_ * KEYD];
__device__ float g_xk[ROWS_ * KEYD];
__device__ float g_xv[ROWS_ * VALD];
__device__ float g_gt[ROWS_ * VALD];
__device__ float g_qn[ROWS_ * KEYD];
__device__ float g_kn[ROWS_ * KEYD];
__device__ float g_vn[ROWS_ * VALD];
__device__ float g_od[ROWS_ * VALD];
__device__ float g_gd[ROWS_ * H_];
__device__ float g_bt[ROWS_ * H_];
__device__ float g_wat[H_ * HID_];
__device__ float g_wbt[H_ * HID_];
// fp16 buffers (activation lo scaled by 2^11); weights hi-only
__device__ __half g_ah[ROWS_ * HID_];
__device__ __half g_al[ROWS_ * HID_];
__device__ __half g_yh[ROWS_ * VALD];
__device__ __half g_yl[ROWS_ * VALD];
__device__ __half g_wqkvh[(2 * KEYD + VALD) * HID_];  // Wq | Wk | Wv rows, [N,K]
__device__ __half g_wgh[VALD * HID_];
__device__ __half g_woh[HID_ * VALD];

// ---------------- packed f32x2 helpers ----------------
__device__ __forceinline__ unsigned long long pk2(float x, float y) {
    unsigned long long r;
    asm("mov.b64 %0, {%1, %2};" : "=l"(r) : "f"(x), "f"(y));
    return r;
}
__device__ __forceinline__ float2 up2(unsigned long long v) {
    float2 r;
    asm("mov.b64 {%0, %1}, %2;" : "=f"(r.x), "=f"(r.y) : "l"(v));
    return r;
}
__device__ __forceinline__ unsigned long long fma2u(unsigned long long a, unsigned long long b, unsigned long long c) {
    unsigned long long d;
    asm("fma.rn.f32x2 %0, %1, %2, %3;" : "=l"(d) : "l"(a), "l"(b), "l"(c));
    return d;
}
__device__ __forceinline__ unsigned long long mul2u(unsigned long long a, unsigned long long b) {
    unsigned long long d;
    asm("mul.rn.f32x2 %0, %1, %2;" : "=l"(d) : "l"(a), "l"(b));
    return d;
}

// ---------------- mma.sync / ldmatrix / cp.async helpers ----------------
__device__ __forceinline__ uint32_t smem_u32(const void* p) {
    uint32_t a;
    asm("{ .reg .u64 t; cvta.to.shared.u64 t, %1; cvt.u32.u64 %0, t; }" : "=r"(a) : "l"(p));
    return a;
}
__device__ __forceinline__ void ldm_x4(uint32_t* r, uint32_t addr) {
    asm volatile("ldmatrix.sync.aligned.m8n8.x4.shared.b16 {%0,%1,%2,%3}, [%4];"
                 : "=r"(r[0]), "=r"(r[1]), "=r"(r[2]), "=r"(r[3]) : "r"(addr));
}
__device__ __forceinline__ void mma_hf32(float* c, const uint32_t* a, const uint32_t* b) {
    asm volatile("mma.sync.aligned.m16n8k16.row.col.f32.f16.f16.f32 "
                 "{%0,%1,%2,%3}, {%4,%5,%6,%7}, {%8,%9}, {%0,%1,%2,%3};"
                 : "+f"(c[0]), "+f"(c[1]), "+f"(c[2]), "+f"(c[3])
                 : "r"(a[0]), "r"(a[1]), "r"(a[2]), "r"(a[3]), "r"(b[0]), "r"(b[1]));
}
__device__ __forceinline__ void mma_hf16(uint32_t* c, const uint32_t* a, const uint32_t* b) {
    asm volatile("mma.sync.aligned.m16n8k16.row.col.f16.f16.f16.f16 "
                 "{%0,%1}, {%2,%3,%4,%5}, {%6,%7}, {%0,%1};"
                 : "+r"(c[0]), "+r"(c[1])
                 : "r"(a[0]), "r"(a[1]), "r"(a[2]), "r"(a[3]), "r"(b[0]), "r"(b[1]));
}
__device__ __forceinline__ void cp16(uint32_t sm, const void* gp) {
    asm volatile("cp.async.cg.shared.global [%0], [%1], 16;" :: "r"(sm), "l"(gp));
}
#define CP_COMMIT() asm volatile("cp.async.commit_group;" ::: "memory")
#define CP_WAIT0()  asm volatile("cp.async.wait_group 0;" ::: "memory")

// ---------------- fp16-split HMMA GEMM tile (2 products), device body ----------------
#define GTILE 18432            // 128 rows * 144 B
#define GBUF  55296            // 3 tiles
#define GEMM_SMEM 110592       // 2 buffers

__device__ __forceinline__ void gemm_tile(
    const __half* __restrict__ Ahi, const __half* __restrict__ Alo,
    const __half* __restrict__ Bhi,
    float* __restrict__ C0, float* __restrict__ C1, float* __restrict__ C2,
    int split1, int split2, int str0, int str1, int str2,
    int K, int bx, int by, char* smem) {
    const uint32_t sbase = smem_u32(smem);
    const int tid = threadIdx.x, lane = tid & 31, wid = tid >> 5;
    const int wm = wid & 1, wn = wid >> 1;      // 2 x 4 warp grid
    const int brow = by * 128, bcol = bx * 128;

    const __half* srcs[3] = {Ahi, Alo, Bhi};
    const int row0[3] = {brow, brow, bcol};

    float accF[4][4][4];
    uint32_t accH[4][4][2];
#pragma unroll
    for (int i = 0; i < 4; i++)
#pragma unroll
        for (int j = 0; j < 4; j++) {
#pragma unroll
            for (int l = 0; l < 4; l++) accF[i][j][l] = 0.f;
            accH[i][j][0] = 0u; accH[i][j][1] = 0u;
        }

    const int r_ = tid >> 3, c8_ = (tid & 7) * 8;

    // prologue: chunk 0 -> buf 0
#pragma unroll
    for (int ts = 0; ts < 3; ts++) {
        const __half* sp = srcs[ts] + (size_t)(row0[ts] + r_) * K + c8_;
        uint32_t tb = sbase + ts * GTILE + r_ * 144 + c8_ * 2;
#pragma unroll
        for (int i = 0; i < 4; i++)
            cp16(tb + i * 32 * 144, sp + (size_t)(i * 32) * K);
    }
    CP_COMMIT();
    CP_WAIT0();
    __syncthreads();

    const int numT = K >> 6;
    const uint32_t a_lane = (lane & 15) * 144 + (lane >> 4) * 16;
    const uint32_t b_lane4 = ((lane & 7) + (lane >> 4) * 8) * 144 + ((lane >> 3) & 1) * 16;

    for (int c = 0; c < numT; c++) {
        const int b = c & 1;
        if (c + 1 < numT) {
            const int kc = (c + 1) << 6, nb = b ^ 1;
#pragma unroll
            for (int ts = 0; ts < 3; ts++) {
                const __half* sp = srcs[ts] + (size_t)(row0[ts] + r_) * K + kc + c8_;
                uint32_t tb = sbase + nb * GBUF + ts * GTILE + r_ * 144 + c8_ * 2;
#pragma unroll
                for (int i = 0; i < 4; i++)
                    cp16(tb + i * 32 * 144, sp + (size_t)(i * 32) * K);
            }
            CP_COMMIT();
        }
        const uint32_t aH = sbase + b * GBUF + wm * 64 * 144;
        const uint32_t aL = aH + GTILE;
        const uint32_t bH = sbase + b * GBUF + 2 * GTILE + wn * 32 * 144;
#pragma unroll
        for (int ks = 0; ks < 4; ks++) {
            const uint32_t acol = ks * 32 + a_lane;
            const uint32_t bcol2 = ks * 32 + b_lane4;
            uint32_t fAH[4][4], fAL[4][4], fBH[4][2];
#pragma unroll
            for (int mt = 0; mt < 4; mt++) {
                ldm_x4(fAH[mt], aH + mt * 16 * 144 + acol);
                ldm_x4(fAL[mt], aL + mt * 16 * 144 + acol);
            }
#pragma unroll
            for (int p = 0; p < 2; p++) {
                uint32_t r4[4];
                ldm_x4(r4, bH + p * 16 * 144 + bcol2);
                fBH[2 * p][0] = r4[0]; fBH[2 * p][1] = r4[1];
                fBH[2 * p + 1][0] = r4[2]; fBH[2 * p + 1][1] = r4[3];
            }
#pragma unroll
            for (int mt = 0; mt < 4; mt++)
#pragma unroll
                for (int nt = 0; nt < 4; nt++) {
                    mma_hf32(accF[mt][nt], fAH[mt], fBH[nt]);
                    mma_hf16(accH[mt][nt], fAL[mt], fBH[nt]);
                }
        }
        CP_WAIT0();
        __syncthreads();
    }

    // epilogue: merge + 3-way route
    float* Cp; int ccol0, strN;
    if (bcol < split1)      { Cp = C0; ccol0 = bcol;          strN = str0; }
    else if (bcol < split2) { Cp = C1; ccol0 = bcol - split1; strN = str1; }
    else                    { Cp = C2; ccol0 = bcol - split2; strN = str2; }
    const int r0 = lane >> 2, cc = (lane & 3) * 2;
#pragma unroll
    for (int mt = 0; mt < 4; mt++)
#pragma unroll
        for (int nt = 0; nt < 4; nt++) {
            float2 lo01 = __half22float2(*(__half2*)&accH[mt][nt][0]);
            float2 lo23 = __half22float2(*(__half2*)&accH[mt][nt][1]);
            size_t base = (size_t)(brow + wm * 64 + mt * 16 + r0) * strN + ccol0 + wn * 32 + nt * 8 + cc;
            *(float2*)&Cp[base] = make_float2(accF[mt][nt][0] + lo01.x * INVLOSCALE,
                                              accF[mt][nt][1] + lo01.y * INVLOSCALE);
            *(float2*)&Cp[base + 8 * (size_t)strN] = make_float2(accF[mt][nt][2] + lo23.x * INVLOSCALE,
                                                                 accF[mt][nt][3] + lo23.y * INVLOSCALE);
        }
}

__global__ __launch_bounds__(256, 1)
void gemm_hx2(const __half* __restrict__ Ahi, const __half* __restrict__ Alo,
              const __half* __restrict__ Bhi,
              float* C0, float* C1, float* C2,
              int split1, int split2, int str0, int str1, int str2, int K) {
    extern __shared__ __align__(16) char smem[];
    gemm_tile(Ahi, Alo, Bhi, C0, C1, C2, split1, split2, str0, str1, str2,
              K, blockIdx.x, blockIdx.y, smem);
}

// ---------------- gated delta rule scan, device body ----------------
// Deferred-decay formulation: within an 8-token window with cumulative decay
// G_t = prod eg, maintain Shat = S / G. Update is ONE fma per 2 elems:
//   pred_t = G_t * (k . Shat_old)
//   delta' = (v - pred)*beta / G_t
//   Shat  += k * delta'        (true S_t = G_t * Shat_t)
//   o_t    = G_t * (q . Shat_t)
// Renormalize S = Shat * G_7 once per window. If G_7 < 1e-12 (uniform scalar),
// fall back to the exact per-token path (identical to R4/R8 math).
__device__ __forceinline__ void scan_body(
    const float* __restrict__ q, const float* __restrict__ k,
    const float* __restrict__ v, const float* __restrict__ g,
    const float* __restrict__ beta, float* __restrict__ o,
    int bi, char* smemc) {
    float (*ks)[272] = (float(*)[272])(smemc);
    float (*qs)[272] = (float(*)[272])(smemc + 8704);
    float (*vs)[DVS] = (float(*)[DVS])(smemc + 17408);
    float* egs = (float*)(smemc + 19456);
    float* bts = (float*)(smemc + 19488);
    float* Gcs = (float*)(smemc + 19520);
    float* ivGs = (float*)(smemc + 19552);
    int* fastf = (int*)(smemc + 19584);

    const int s = bi & 7;
    const int h = (bi >> 3) % H_;
    const int b = bi / (H_ * NSL);
    const int tid = threadIdx.x;
    const int vl = tid >> 2, kseg = tid & 3;
    const int sidx = (tid >> 6) * 68 + (tid & 63);

    unsigned long long S[32];
#pragma unroll
    for (int m = 0; m < 32; m++) S[m] = 0ull;

    for (int t0 = 0; t0 < T_; t0 += TOKB) {
#pragma unroll
        for (int tt = 0; tt < TOKB; tt++) {
            size_t base = ((size_t)(b * T_ + t0 + tt) * H_ + h) * DKH;
            ks[tt][sidx] = k[base + tid];
            qs[tt][sidx] = q[base + tid];
        }
#pragma unroll
        for (int i = 0; i < 2; i++) {
            int ee = i * 256 + tid;
            int tt = ee >> 6, vle = ee & 63;
            vs[tt][vle] = v[((size_t)(b * T_ + t0 + tt) * H_ + h) * DVH + s * DVS + vle];
        }
        if (tid < TOKB) {
            size_t gi = (size_t)(b * T_ + t0 + tid) * H_ + h;
            egs[tid] = expf(g[gi]);
            bts[tid] = beta[gi];
        }
        __syncthreads();
        if (tid == 0) {
            float Gp = 1.f;
#pragma unroll
            for (int i = 0; i < TOKB; i++) {
                Gp *= egs[i];
                Gcs[i] = Gp;
                ivGs[i] = 1.f / Gp;
            }
            *fastf = (Gp >= 1e-12f) ? 1 : 0;
        }
        __syncthreads();

        if (*fastf) {
            // ---- fast path: deferred decay, single-fma updates ----
#pragma unroll 1
            for (int tt = 0; tt < TOKB; tt++) {
                const float Gt = Gcs[tt], iv = ivGs[tt], bt = bts[tt], vv = vs[tt][vl];
                const ulonglong2* kp2 = (const ulonglong2*)&ks[tt][kseg * 68];
                const ulonglong2* qp2 = (const ulonglong2*)&qs[tt][kseg * 68];

                ulonglong2 kv[16];
                unsigned long long a0 = 0ull, a1 = 0ull;
#pragma unroll
                for (int m = 0; m < 16; m++) {
                    kv[m] = kp2[m];
                    a0 = fma2u(kv[m].x, S[2 * m], a0);
                    a1 = fma2u(kv[m].y, S[2 * m + 1], a1);
                }
                float2 f0 = up2(a0), f1 = up2(a1);
                float pred = f0.x + f0.y + f1.x + f1.y;
                pred += __shfl_xor_sync(0xffffffffu, pred, 1);
                pred += __shfl_xor_sync(0xffffffffu, pred, 2);
                pred *= Gt;
                const float dG = (vv - pred) * bt * iv;
                const unsigned long long d2 = pk2(dG, dG);

                unsigned long long o0 = 0ull, o1 = 0ull;
#pragma unroll
                for (int m = 0; m < 16; m++) {
                    ulonglong2 qv = qp2[m];
                    unsigned long long s0 = fma2u(kv[m].x, d2, S[2 * m]);
                    unsigned long long s1 = fma2u(kv[m].y, d2, S[2 * m + 1]);
                    S[2 * m] = s0;
                    S[2 * m + 1] = s1;
                    o0 = fma2u(qv.x, s0, o0);
                    o1 = fma2u(qv.y, s1, o1);
                }
                float2 g0 = up2(o0), g1 = up2(o1);
                float ov = g0.x + g0.y + g1.x + g1.y;
                ov += __shfl_xor_sync(0xffffffffu, ov, 1);
                ov += __shfl_xor_sync(0xffffffffu, ov, 2);
                ov *= Gt;
                if (kseg == 0)
                    o[((size_t)(b * T_ + t0 + tt) * H_ + h) * DVH + s * DVS + vl] = ov;
            }
            // window-end renormalization: S = Shat * G7
            {
                const float G7 = Gcs[TOKB - 1];
                const unsigned long long G72 = pk2(G7, G7);
#pragma unroll
                for (int m = 0; m < 32; m++) S[m] = mul2u(S[m], G72);
            }
        } else {
            // ---- exact fallback (original per-token decay) ----
#pragma unroll 1
            for (int tt = 0; tt < TOKB; tt++) {
                float eg = egs[tt], bt = bts[tt], vv = vs[tt][vl];
                const float4* kp = (const float4*)&ks[tt][kseg * 68];
                const float4* qp = (const float4*)&qs[tt][kseg * 68];

                unsigned long long a0 = 0ull, a1 = 0ull;
#pragma unroll
                for (int m4 = 0; m4 < 16; m4++) {
                    float4 k4 = kp[m4];
                    a0 = fma2u(pk2(k4.x, k4.y), S[2 * m4], a0);
                    a1 = fma2u(pk2(k4.z, k4.w), S[2 * m4 + 1], a1);
                }
                float2 f0 = up2(a0), f1 = up2(a1);
                float pred = f0.x + f0.y + f1.x + f1.y;
                pred += __shfl_xor_sync(0xffffffffu, pred, 1);
                pred += __shfl_xor_sync(0xffffffffu, pred, 2);
                pred *= eg;
                float delta = (vv - pred) * bt;

                unsigned long long eg2 = pk2(eg, eg), d2 = pk2(delta, delta);
                unsigned long long o0 = 0ull, o1 = 0ull;
#pragma unroll
                for (int m4 = 0; m4 < 16; m4++) {
                    float4 k4 = kp[m4];
                    float4 q4 = qp[m4];
                    unsigned long long s0 = fma2u(pk2(k4.x, k4.y), d2, mul2u(eg2, S[2 * m4]));
                    unsigned long long s1 = fma2u(pk2(k4.z, k4.w), d2, mul2u(eg2, S[2 * m4 + 1]));
                    S[2 * m4] = s0;
                    S[2 * m4 + 1] = s1;
                    o0 = fma2u(pk2(q4.x, q4.y), s0, o0);
                    o1 = fma2u(pk2(q4.z, q4.w), s1, o1);
                }
                float2 g0 = up2(o0), g1 = up2(o1);
                float ov = g0.x + g0.y + g1.x + g1.y;
                ov += __shfl_xor_sync(0xffffffffu, ov, 1);
                ov += __shfl_xor_sync(0xffffffffu, ov, 2);
                if (kseg == 0)
                    o[((size_t)(b * T_ + t0 + tt) * H_ + h) * DVH + s * DVS + vl] = ov;
            }
        }
        __syncthreads();
    }
}

// ---------------- fat kernel: scan (96 CTAs) + gate GEMM (1536 CTAs) ----------------
__global__ __launch_bounds__(256, 1)
void scan_gemm(const float* __restrict__ qn, const float* __restrict__ kn,
               const float* __restrict__ vn, const float* __restrict__ gd,
               const float* __restrict__ bt, float* __restrict__ od,
               const __half* __restrict__ ah, const __half* __restrict__ al,
               const __half* __restrict__ wgh, float* __restrict__ gt) {
    extern __shared__ __align__(16) char smem[];
    if (blockIdx.x < SCAN_CTAS) {
        scan_body(qn, kn, vn, gd, bt, od, blockIdx.x, smem);
    } else {
        int gi = blockIdx.x - SCAN_CTAS;
        gemm_tile(ah, al, wgh, gt, gt, gt, VALD, VALD, VALD, VALD, VALD,
                  HID_, gi % (VALD / 128), gi / (VALD / 128), smem);
    }
}

// ---------------- fp32 -> fp16 hi/lo split (lo scaled by 2^11) ----------------
__global__ void split4(const float* __restrict__ x, __half* __restrict__ xh,
                       __half* __restrict__ xl) {
    int i4 = blockIdx.x * 256 + threadIdx.x;
    float4 v = ((const float4*)x)[i4];
    __half h0 = __float2half_rn(v.x), h1 = __float2half_rn(v.y);
    __half h2 = __float2half_rn(v.z), h3 = __float2half_rn(v.w);
    __half l0 = __float2half_rn((v.x - __half2float(h0)) * LOSCALE);
    __half l1 = __float2half_rn((v.y - __half2float(h1)) * LOSCALE);
    __half l2 = __float2half_rn((v.z - __half2float(h2)) * LOSCALE);
    __half l3 = __float2half_rn((v.w - __half2float(h3)) * LOSCALE);
    __half2* hp = (__half2*)(xh + (size_t)i4 * 4);
    __half2* lp = (__half2*)(xl + (size_t)i4 * 4);
    hp[0] = __halves2half2(h0, h1); hp[1] = __halves2half2(h2, h3);
    lp[0] = __halves2half2(l0, l1); lp[1] = __halves2half2(l2, l3);
}

// ---------------- weight transpose: W[K,N] -> Wh [N,K] fp16 (hi only) ----------------
__global__ void tsplit1(const float* __restrict__ W, __half* __restrict__ Wh, int K, int N) {
    __shared__ float tile[32][33];
    int n0 = blockIdx.x * 32, k0 = blockIdx.y * 32;
    int tx = threadIdx.x & 31, ty = threadIdx.x >> 5;   // 32x8
#pragma unroll
    for (int i = 0; i < 4; i++) {
        int k = k0 + ty + i * 8;
        tile[ty + i * 8][tx] = W[(size_t)k * N + n0 + tx];
    }
    __syncthreads();
#pragma unroll
    for (int i = 0; i < 4; i++) {
        int n = n0 + ty + i * 8;
        Wh[(size_t)n * K + k0 + tx] = __float2half_rn(tile[tx][ty + i * 8]);
    }
}

// ---------------- fused causal depthwise conv (K=4) + SiLU for q,k,v ----------------
__global__ void conv_silu_all(const float* __restrict__ xq, const float* __restrict__ xk,
                              const float* __restrict__ xv,
                              const float* __restrict__ wq, const float* __restrict__ wk,
                              const float* __restrict__ wv,
                              float* __restrict__ yq, float* __restrict__ yk,
                              float* __restrict__ yv) {
    int idx = blockIdx.x * 256 + threadIdx.x;
    const float* x; const float* w; float* y; int D;
    const int NQ = ROWS_ * KEYD;
    if (idx < NQ)           { x = xq; w = wq; y = yq; D = KEYD; }
    else if (idx < 2 * NQ)  { idx -= NQ; x = xk; w = wk; y = yk; D = KEYD; }
    else                    { idx -= 2 * NQ; x = xv; w = wv; y = yv; D = VALD; }
    int d = idx % D;
    int t = (idx / D) & (T_ - 1);
    float4 wvv = *(const float4*)(w + d * 4);
    float acc = x[idx] * wvv.w;
    if (t >= 1) acc += x[idx - D] * wvv.z;
    if (t >= 2) acc += x[idx - 2 * D] * wvv.y;
    if (t >= 3) acc += x[idx - 3 * D] * wvv.x;
    y[idx] = acc / (1.f + expf(-acc));
}

// ---------------- fused per-(b,t,h) L2 norm over 256 for q (x1/16) and k ----------------
__global__ void l2norm_qk(float* __restrict__ q, float* __restrict__ k) {
    int gw = (blockIdx.x * 256 + threadIdx.x) >> 5;
    int lane = threadIdx.x & 31;
    const int NR = ROWS_ * H_;
    float scale; float* x;
    if (gw < NR) { x = q; scale = 0.0625f; }
    else         { x = k; gw -= NR; scale = 1.0f; }
    float* row = x + (size_t)gw * DKH;
    float4 v0 = *(const float4*)(row + lane * 8);
    float4 v1 = *(const float4*)(row + lane * 8 + 4);
    float ss = v0.x * v0.x + v0.y * v0.y + v0.z * v0.z + v0.w * v0.w +
               v1.x * v1.x + v1.y * v1.y + v1.z * v1.z + v1.w * v1.w;
#pragma unroll
    for (int o = 16; o; o >>= 1) ss += __shfl_xor_sync(0xffffffffu, ss, o);
    float r = rsqrtf(ss) * scale;
    v0.x *= r; v0.y *= r; v0.z *= r; v0.w *= r;
    v1.x *= r; v1.y *= r; v1.z *= r; v1.w *= r;
    *(float4*)(row + lane * 8) = v0;
    *(float4*)(row + lane * 8 + 4) = v1;
}

// ---------------- transpose Wa/Wb (2048x6 -> 6x2048) ----------------
__global__ void transpose6(const float* __restrict__ Wa, const float* __restrict__ Wb,
                           float* __restrict__ WaT, float* __restrict__ WbT) {
    int i = blockIdx.x * 256 + threadIdx.x;
    int c = i / H_, h = i % H_;
    WaT[h * HID_ + c] = Wa[i];
    WbT[h * HID_ + c] = Wb[i];
}

// ---------------- beta / decay projection ----------------
__global__ void proj_ab(const float* __restrict__ hid, const float* __restrict__ WaT,
                        const float* __restrict__ WbT, const float* __restrict__ A_log,
                        const float* __restrict__ dt_bias,
                        float* __restrict__ gdec, float* __restrict__ beta) {
    int gw = (blockIdx.x * 256 + threadIdx.x) >> 5;
    int lane = threadIdx.x & 31;
    const float* hr = hid + (size_t)gw * HID_;
    float da0 = 0, da1 = 0, da2 = 0, da3 = 0, da4 = 0, da5 = 0;
    float db0 = 0, db1 = 0, db2 = 0, db3 = 0, db4 = 0, db5 = 0;
    for (int c = lane; c < HID_; c += 32) {
        float hv = hr[c];
        da0 += hv * WaT[0 * HID_ + c]; db0 += hv * WbT[0 * HID_ + c];
        da1 += hv * WaT[1 * HID_ + c]; db1 += hv * WbT[1 * HID_ + c];
        da2 += hv * WaT[2 * HID_ + c]; db2 += hv * WbT[2 * HID_ + c];
        da3 += hv * WaT[3 * HID_ + c]; db3 += hv * WbT[3 * HID_ + c];
        da4 += hv * WaT[4 * HID_ + c]; db4 += hv * WbT[4 * HID_ + c];
        da5 += hv * WaT[5 * HID_ + c]; db5 += hv * WbT[5 * HID_ + c];
    }
#pragma unroll
    for (int o = 16; o; o >>= 1) {
        da0 += __shfl_xor_sync(~0u, da0, o); db0 += __shfl_xor_sync(~0u, db0, o);
        da1 += __shfl_xor_sync(~0u, da1, o); db1 += __shfl_xor_sync(~0u, db1, o);
        da2 += __shfl_xor_sync(~0u, da2, o); db2 += __shfl_xor_sync(~0u, db2, o);
        da3 += __shfl_xor_sync(~0u, da3, o); db3 += __shfl_xor_sync(~0u, db3, o);
        da4 += __shfl_xor_sync(~0u, da4, o); db4 += __shfl_xor_sync(~0u, db4, o);
        da5 += __shfl_xor_sync(~0u, da5, o); db5 += __shfl_xor_sync(~0u, db5, o);
    }
    if (lane == 0) {
        float da[6] = {da0, da1, da2, da3, da4, da5};
        float db[6] = {db0, db1, db2, db3, db4, db5};
#pragma unroll
        for (int h = 0; h < 6; h++) {
            float x = da[h] + dt_bias[h];
            float sp = (x > 20.f) ? x : log1pf(expf(x));
            gdec[gw * H_ + h] = -expf(A_log[h]) * sp;
            beta[gw * H_ + h] = 1.f / (1.f + expf(-db[h]));
        }
    }
}

// ---------------- RMSNorm * weight * silu(gate) -> fp16 hi/lo split ----------------
__global__ void norm_gate(const float* __restrict__ o, const float* __restrict__ gate,
                          const float* __restrict__ nw,
                          __half* __restrict__ yh, __half* __restrict__ yl) {
    int gw = (blockIdx.x * 256 + threadIdx.x) >> 5;
    int lane = threadIdx.x & 31;
    size_t base = (size_t)gw * DVH;
    float4 v[4];
    float ss = 0.f;
#pragma unroll
    for (int i = 0; i < 4; i++) {
        v[i] = *(const float4*)(o + base + (lane + i * 32) * 4);
        ss += v[i].x * v[i].x + v[i].y * v[i].y + v[i].z * v[i].z + v[i].w * v[i].w;
    }
#pragma unroll
    for (int off = 16; off; off >>= 1) ss += __shfl_xor_sync(0xffffffffu, ss, off);
    float r = rsqrtf(ss * (1.f / 512.f) + 1e-5f);
#pragma unroll
    for (int i = 0; i < 4; i++) {
        int d4 = (lane + i * 32) * 4;
        float4 gt = *(const float4*)(gate + base + d4);
        float4 w = *(const float4*)(nw + d4);
        float o0 = v[i].x * r * w.x * (gt.x / (1.f + expf(-gt.x)));
        float o1 = v[i].y * r * w.y * (gt.y / (1.f + expf(-gt.y)));
        float o2 = v[i].z * r * w.z * (gt.z / (1.f + expf(-gt.z)));
        float o3 = v[i].w * r * w.w * (gt.w / (1.f + expf(-gt.w)));
        __half h0 = __float2half_rn(o0), h1 = __float2half_rn(o1);
        __half h2 = __float2half_rn(o2), h3 = __float2half_rn(o3);
        __half2* hp = (__half2*)(yh + base + d4);
        __half2* lp = (__half2*)(yl + base + d4);
        hp[0] = __halves2half2(h0, h1);
        hp[1] = __halves2half2(h2, h3);
        lp[0] = __halves2half2(__float2half_rn((o0 - __half2float(h0)) * LOSCALE),
                               __float2half_rn((o1 - __half2float(h1)) * LOSCALE));
        lp[1] = __halves2half2(__float2half_rn((o2 - __half2float(h2)) * LOSCALE),
                               __float2half_rn((o3 - __half2float(h3)) * LOSCALE));
    }
}

// ---------------- launch ----------------
extern "C" void kernel_launch(void* const* d_in, const int* in_sizes, int n_in,
                              void* d_out, int out_size) {
    const float* hid  = (const float*)d_in[0];
    const float* Wq   = (const float*)d_in[1];
    const float* Wk   = (const float*)d_in[2];
    const float* Wv   = (const float*)d_in[3];
    const float* Wa   = (const float*)d_in[4];
    const float* Wb   = (const float*)d_in[5];
    const float* Wg   = (const float*)d_in[6];
    const float* Wo   = (const float*)d_in[7];
    const float* cwq  = (const float*)d_in[8];
    const float* cwk  = (const float*)d_in[9];
    const float* cwv  = (const float*)d_in[10];
    const float* Alog = (const float*)d_in[11];
    const float* dtb  = (const float*)d_in[12];
    const float* nw   = (const float*)d_in[13];

    float *xq, *xk, *xv, *gt, *qn, *kn, *vn, *od, *gd, *bt, *wat, *wbt;
    __half *ah, *al, *yh, *yl, *wqkvh, *wgh, *woh;
    cudaGetSymbolAddress((void**)&xq, g_xq);
    cudaGetSymbolAddress((void**)&xk, g_xk);
    cudaGetSymbolAddress((void**)&xv, g_xv);
    cudaGetSymbolAddress((void**)&gt, g_gt);
    cudaGetSymbolAddress((void**)&qn, g_qn);
    cudaGetSymbolAddress((void**)&kn, g_kn);
    cudaGetSymbolAddress((void**)&vn, g_vn);
    cudaGetSymbolAddress((void**)&od, g_od);
    cudaGetSymbolAddress((void**)&gd, g_gd);
    cudaGetSymbolAddress((void**)&bt, g_bt);
    cudaGetSymbolAddress((void**)&wat, g_wat);
    cudaGetSymbolAddress((void**)&wbt, g_wbt);
    cudaGetSymbolAddress((void**)&ah, g_ah);
    cudaGetSymbolAddress((void**)&al, g_al);
    cudaGetSymbolAddress((void**)&yh, g_yh);
    cudaGetSymbolAddress((void**)&yl, g_yl);
    cudaGetSymbolAddress((void**)&wqkvh, g_wqkvh);
    cudaGetSymbolAddress((void**)&wgh, g_wgh);
    cudaGetSymbolAddress((void**)&woh, g_woh);

    cudaFuncSetAttribute(gemm_hx2, cudaFuncAttributeMaxDynamicSharedMemorySize, GEMM_SMEM);
    cudaFuncSetAttribute(scan_gemm, cudaFuncAttributeMaxDynamicSharedMemorySize, GEMM_SMEM);

    // fp16 prep: activations (hi+lo) + weights (hi only, transposed to [N,K])
    split4<<<(ROWS_ * HID_ / 4) / 256, 256>>>(hid, ah, al);
    tsplit1<<<dim3(KEYD / 32, HID_ / 32), 256>>>(Wq, wqkvh, HID_, KEYD);
    tsplit1<<<dim3(KEYD / 32, HID_ / 32), 256>>>(Wk, wqkvh + (size_t)KEYD * HID_, HID_, KEYD);
    tsplit1<<<dim3(VALD / 32, HID_ / 32), 256>>>(Wv, wqkvh + (size_t)2 * KEYD * HID_, HID_, VALD);
    tsplit1<<<dim3(VALD / 32, HID_ / 32), 256>>>(Wg, wgh, HID_, VALD);
    tsplit1<<<dim3(HID_ / 32, VALD / 32), 256>>>(Wo, woh, VALD, HID_);

    // beta / decay (before the fat kernel)
    transpose6<<<(H_ * HID_) / 256, 256>>>(Wa, Wb, wat, wbt);
    proj_ab<<<(ROWS_ * 32) / 256, 256>>>(hid, wat, wbt, Alog, dtb, gd, bt);

    // fused Q|K|V projection (N = 6144, 3-way routed epilogue)
    gemm_hx2<<<dim3((2 * KEYD + VALD) / 128, ROWS_ / 128), 256, GEMM_SMEM>>>(
        ah, al, wqkvh, xq, xk, xv, KEYD, 2 * KEYD, KEYD, KEYD, VALD, HID_);

    // fused conv + silu (q,k,v in one launch)
    conv_silu_all<<<(ROWS_ * (2 * KEYD + VALD)) / 256, 256>>>(
        xq, xk, xv, cwq, cwk, cwv, qn, kn, vn);

    // fused l2 norms (q scaled by 1/16, k unit)
    l2norm_qk<<<(2 * ROWS_ * H_ * 32) / 256, 256>>>(qn, kn);

    // fat kernel: scan on 96 CTAs + gate GEMM (Wg) backfilling idle SMs
    scan_gemm<<<SCAN_CTAS + (VALD / 128) * (ROWS_ / 128), 256, GEMM_SMEM>>>(
        qn, kn, vn, gd, bt, od, ah, al, wgh, gt);

    // rmsnorm * weight * silu(gate) -> fp16 hi/lo
    norm_gate<<<(ROWS_ * H_ * 32) / 256, 256>>>(od, gt, nw, yh, yl);

    // output projection -> d_out
    gemm_hx2<<<dim3(HID_ / 128, ROWS_ / 128), 256, GEMM_SMEM>>>(
        yh, yl, woh, (float*)d_out, (float*)d_out, (float*)d_out,
        HID_, HID_, HID_, HID_, HID_, VALD);
}

// round 12
// speedup vs baseline: 1.0436x; 1.0436x over previous
#include <cuda_runtime.h>
#include <cuda_fp16.h>
#include <math.h>
#include <stdint.h>

// ---------------- problem constants ----------------
#define B_ 2
#define T_ 4096
#define HID_ 2048
#define H_ 6
#define DKH 256
#define DVH 512
#define KEYD 1536
#define VALD 3072
#define ROWS_ (B_ * T_)          // 8192
#define DVS 64                   // dv slice per scan CTA
#define NSL 8                    // 512/64
#define TOKB 8                   // tokens staged per scan round
#define LOSCALE 2048.0f
#define INVLOSCALE (1.0f / 2048.0f)
#define SCAN_CTAS (B_ * H_ * NSL)   // 96

// ---------------- scratch (device globals; no allocation allowed) ----------------
__device__ float g_xq[ROWS_ * KEYD];
__device__ float g_xk[ROWS_ * KEYD];
__device__ float g_xv[ROWS_ * VALD];
__device__ float g_gt[ROWS_ * VALD];
__device__ float g_qn[ROWS_ * KEYD];
__device__ float g_kn[ROWS_ * KEYD];
__device__ float g_vn[ROWS_ * VALD];
__device__ float g_od[ROWS_ * VALD];
__device__ float g_gd[ROWS_ * H_];
__device__ float g_bt[ROWS_ * H_];
__device__ float g_wat[H_ * HID_];
__device__ float g_wbt[H_ * HID_];
// fp16 buffers (activation lo scaled by 2^11); weights hi-only
__device__ __half g_ah[ROWS_ * HID_];
__device__ __half g_al[ROWS_ * HID_];
__device__ __half g_yh[ROWS_ * VALD];
__device__ __half g_yl[ROWS_ * VALD];
__device__ __half g_wqkvh[(2 * KEYD + VALD) * HID_];  // Wq | Wk | Wv rows, [N,K]
__device__ __half g_wgh[VALD * HID_];
__device__ __half g_woh[HID_ * VALD];

// ---------------- packed f32x2 helpers ----------------
__device__ __forceinline__ unsigned long long pk2(float x, float y) {
    unsigned long long r;
    asm("mov.b64 %0, {%1, %2};" : "=l"(r) : "f"(x), "f"(y));
    return r;
}
__device__ __forceinline__ float2 up2(unsigned long long v) {
    float2 r;
    asm("mov.b64 {%0, %1}, %2;" : "=f"(r.x), "=f"(r.y) : "l"(v));
    return r;
}
__device__ __forceinline__ unsigned long long fma2u(unsigned long long a, unsigned long long b, unsigned long long c) {
    unsigned long long d;
    asm("fma.rn.f32x2 %0, %1, %2, %3;" : "=l"(d) : "l"(a), "l"(b), "l"(c));
    return d;
}
__device__ __forceinline__ unsigned long long mul2u(unsigned long long a, unsigned long long b) {
    unsigned long long d;
    asm("mul.rn.f32x2 %0, %1, %2;" : "=l"(d) : "l"(a), "l"(b));
    return d;
}

// ---------------- mma.sync / ldmatrix / cp.async helpers ----------------
__device__ __forceinline__ uint32_t smem_u32(const void* p) {
    uint32_t a;
    asm("{ .reg .u64 t; cvta.to.shared.u64 t, %1; cvt.u32.u64 %0, t; }" : "=r"(a) : "l"(p));
    return a;
}
__device__ __forceinline__ void ldm_x4(uint32_t* r, uint32_t addr) {
    asm volatile("ldmatrix.sync.aligned.m8n8.x4.shared.b16 {%0,%1,%2,%3}, [%4];"
                 : "=r"(r[0]), "=r"(r[1]), "=r"(r[2]), "=r"(r[3]) : "r"(addr));
}
__device__ __forceinline__ void mma_hf32(float* c, const uint32_t* a, const uint32_t* b) {
    asm volatile("mma.sync.aligned.m16n8k16.row.col.f32.f16.f16.f32 "
                 "{%0,%1,%2,%3}, {%4,%5,%6,%7}, {%8,%9}, {%0,%1,%2,%3};"
                 : "+f"(c[0]), "+f"(c[1]), "+f"(c[2]), "+f"(c[3])
                 : "r"(a[0]), "r"(a[1]), "r"(a[2]), "r"(a[3]), "r"(b[0]), "r"(b[1]));
}
__device__ __forceinline__ void mma_hf16(uint32_t* c, const uint32_t* a, const uint32_t* b) {
    asm volatile("mma.sync.aligned.m16n8k16.row.col.f16.f16.f16.f16 "
                 "{%0,%1}, {%2,%3,%4,%5}, {%6,%7}, {%0,%1};"
                 : "+r"(c[0]), "+r"(c[1])
                 : "r"(a[0]), "r"(a[1]), "r"(a[2]), "r"(a[3]), "r"(b[0]), "r"(b[1]));
}
__device__ __forceinline__ void cp16(uint32_t sm, const void* gp) {
    asm volatile("cp.async.cg.shared.global [%0], [%1], 16;" :: "r"(sm), "l"(gp));
}
#define CP_COMMIT() asm volatile("cp.async.commit_group;" ::: "memory")
#define CP_WAIT0()  asm volatile("cp.async.wait_group 0;" ::: "memory")
#define CP_WAIT1()  asm volatile("cp.async.wait_group 1;" ::: "memory")

// ---------------- fp16-split HMMA GEMM tile (2 products), 3-stage pipeline ----------------
// C = Ah*Bh (f32 acc) + 2^-11 * (Al'*Bh) (f16 acc); B [N,K] hi-only.
// CTA 128x128, 256 threads, warp tile 64x32, K-chunk 64, cp.async 3-stage:
// 2 chunks in flight, wait_group 1 per iteration -> load latency hidden behind
// a full chunk of compute instead of exposed per chunk.
#define GTILE 18432            // 128 rows * 144 B
#define GBUF  55296            // 3 tiles
#define GEMM_SMEM 165888       // 3 stages

__device__ __forceinline__ void gemm_ldchunk(
    const __half* const* srcs, const int* row0, int K, int kc,
    uint32_t sbase_buf, int r_, int c8_) {
#pragma unroll
    for (int ts = 0; ts < 3; ts++) {
        const __half* sp = srcs[ts] + (size_t)(row0[ts] + r_) * K + kc + c8_;
        uint32_t tb = sbase_buf + ts * GTILE + r_ * 144 + c8_ * 2;
#pragma unroll
        for (int i = 0; i < 4; i++)
            cp16(tb + i * 32 * 144, sp + (size_t)(i * 32) * K);
    }
}

__device__ __forceinline__ void gemm_tile(
    const __half* __restrict__ Ahi, const __half* __restrict__ Alo,
    const __half* __restrict__ Bhi,
    float* __restrict__ C0, float* __restrict__ C1, float* __restrict__ C2,
    int split1, int split2, int str0, int str1, int str2,
    int K, int bx, int by, char* smem) {
    const uint32_t sbase = smem_u32(smem);
    const int tid = threadIdx.x, lane = tid & 31, wid = tid >> 5;
    const int wm = wid & 1, wn = wid >> 1;      // 2 x 4 warp grid
    const int brow = by * 128, bcol = bx * 128;

    const __half* srcs[3] = {Ahi, Alo, Bhi};
    const int row0[3] = {brow, brow, bcol};

    float accF[4][4][4];
    uint32_t accH[4][4][2];
#pragma unroll
    for (int i = 0; i < 4; i++)
#pragma unroll
        for (int j = 0; j < 4; j++) {
#pragma unroll
            for (int l = 0; l < 4; l++) accF[i][j][l] = 0.f;
            accH[i][j][0] = 0u; accH[i][j][1] = 0u;
        }

    const int r_ = tid >> 3, c8_ = (tid & 7) * 8;
    const int numT = K >> 6;

    // prologue: chunks 0 and 1 in flight
    gemm_ldchunk(srcs, row0, K, 0, sbase, r_, c8_);
    CP_COMMIT();
    if (numT > 1) {
        gemm_ldchunk(srcs, row0, K, 64, sbase + GBUF, r_, c8_);
        CP_COMMIT();
    }

    const uint32_t a_lane = (lane & 15) * 144 + (lane >> 4) * 16;
    const uint32_t b_lane4 = ((lane & 7) + (lane >> 4) * 8) * 144 + ((lane >> 3) & 1) * 16;

    int buf = 0;
    for (int c = 0; c < numT; c++) {
        if (c + 1 < numT) CP_WAIT1(); else CP_WAIT0();
        __syncthreads();   // chunk c visible; all threads done computing c-1
        if (c + 2 < numT) {
            int nb = buf + 2; if (nb >= 3) nb -= 3;
            gemm_ldchunk(srcs, row0, K, (c + 2) << 6, sbase + nb * GBUF, r_, c8_);
            CP_COMMIT();
        }
        const uint32_t aH = sbase + buf * GBUF + wm * 64 * 144;
        const uint32_t aL = aH + GTILE;
        const uint32_t bH = sbase + buf * GBUF + 2 * GTILE + wn * 32 * 144;
#pragma unroll
        for (int ks = 0; ks < 4; ks++) {
            const uint32_t acol = ks * 32 + a_lane;
            const uint32_t bcol2 = ks * 32 + b_lane4;
            uint32_t fAH[4][4], fAL[4][4], fBH[4][2];
#pragma unroll
            for (int mt = 0; mt < 4; mt++) {
                ldm_x4(fAH[mt], aH + mt * 16 * 144 + acol);
                ldm_x4(fAL[mt], aL + mt * 16 * 144 + acol);
            }
#pragma unroll
            for (int p = 0; p < 2; p++) {
                uint32_t r4[4];
                ldm_x4(r4, bH + p * 16 * 144 + bcol2);
                fBH[2 * p][0] = r4[0]; fBH[2 * p][1] = r4[1];
                fBH[2 * p + 1][0] = r4[2]; fBH[2 * p + 1][1] = r4[3];
            }
#pragma unroll
            for (int mt = 0; mt < 4; mt++)
#pragma unroll
                for (int nt = 0; nt < 4; nt++) {
                    mma_hf32(accF[mt][nt], fAH[mt], fBH[nt]);
                    mma_hf16(accH[mt][nt], fAL[mt], fBH[nt]);
                }
        }
        if (++buf >= 3) buf = 0;
    }

    // epilogue: merge f32 main + f16 correction, 3-way route
    float* Cp; int ccol0, strN;
    if (bcol < split1)      { Cp = C0; ccol0 = bcol;          strN = str0; }
    else if (bcol < split2) { Cp = C1; ccol0 = bcol - split1; strN = str1; }
    else                    { Cp = C2; ccol0 = bcol - split2; strN = str2; }
    const int r0 = lane >> 2, cc = (lane & 3) * 2;
#pragma unroll
    for (int mt = 0; mt < 4; mt++)
#pragma unroll
        for (int nt = 0; nt < 4; nt++) {
            float2 lo01 = __half22float2(*(__half2*)&accH[mt][nt][0]);
            float2 lo23 = __half22float2(*(__half2*)&accH[mt][nt][1]);
            size_t base = (size_t)(brow + wm * 64 + mt * 16 + r0) * strN + ccol0 + wn * 32 + nt * 8 + cc;
            *(float2*)&Cp[base] = make_float2(accF[mt][nt][0] + lo01.x * INVLOSCALE,
                                              accF[mt][nt][1] + lo01.y * INVLOSCALE);
            *(float2*)&Cp[base + 8 * (size_t)strN] = make_float2(accF[mt][nt][2] + lo23.x * INVLOSCALE,
                                                                 accF[mt][nt][3] + lo23.y * INVLOSCALE);
        }
}

__global__ __launch_bounds__(256, 1)
void gemm_hx2(const __half* __restrict__ Ahi, const __half* __restrict__ Alo,
              const __half* __restrict__ Bhi,
              float* C0, float* C1, float* C2,
              int split1, int split2, int str0, int str1, int str2, int K) {
    extern __shared__ __align__(16) char smem[];
    gemm_tile(Ahi, Alo, Bhi, C0, C1, C2, split1, split2, str0, str1, str2,
              K, blockIdx.x, blockIdx.y, smem);
}

// ---------------- gated delta rule scan, device body (R8 known-good) ----------------
__device__ __forceinline__ void scan_body(
    const float* __restrict__ q, const float* __restrict__ k,
    const float* __restrict__ v, const float* __restrict__ g,
    const float* __restrict__ beta, float* __restrict__ o,
    int bi, char* smemc) {
    float (*ks)[272] = (float(*)[272])(smemc);
    float (*qs)[272] = (float(*)[272])(smemc + 8704);
    float (*vs)[DVS] = (float(*)[DVS])(smemc + 17408);
    float* egs = (float*)(smemc + 19456);
    float* bts = (float*)(smemc + 19488);

    const int s = bi & 7;
    const int h = (bi >> 3) % H_;
    const int b = bi / (H_ * NSL);
    const int tid = threadIdx.x;
    const int vl = tid >> 2, kseg = tid & 3;
    const int sidx = (tid >> 6) * 68 + (tid & 63);

    unsigned long long S[32];
#pragma unroll
    for (int m = 0; m < 32; m++) S[m] = 0ull;

    for (int t0 = 0; t0 < T_; t0 += TOKB) {
#pragma unroll
        for (int tt = 0; tt < TOKB; tt++) {
            size_t base = ((size_t)(b * T_ + t0 + tt) * H_ + h) * DKH;
            ks[tt][sidx] = k[base + tid];
            qs[tt][sidx] = q[base + tid];
        }
#pragma unroll
        for (int i = 0; i < 2; i++) {
            int ee = i * 256 + tid;
            int tt = ee >> 6, vle = ee & 63;
            vs[tt][vle] = v[((size_t)(b * T_ + t0 + tt) * H_ + h) * DVH + s * DVS + vle];
        }
        if (tid < TOKB) {
            size_t gi = (size_t)(b * T_ + t0 + tid) * H_ + h;
            egs[tid] = expf(g[gi]);
            bts[tid] = beta[gi];
        }
        __syncthreads();

#pragma unroll 1
        for (int tt = 0; tt < TOKB; tt++) {
            float eg = egs[tt], bt = bts[tt], vv = vs[tt][vl];
            const float4* kp = (const float4*)&ks[tt][kseg * 68];
            const float4* qp = (const float4*)&qs[tt][kseg * 68];

            unsigned long long a0 = 0ull, a1 = 0ull;
#pragma unroll
            for (int m4 = 0; m4 < 16; m4++) {
                float4 k4 = kp[m4];
                a0 = fma2u(pk2(k4.x, k4.y), S[2 * m4], a0);
                a1 = fma2u(pk2(k4.z, k4.w), S[2 * m4 + 1], a1);
            }
            float2 f0 = up2(a0), f1 = up2(a1);
            float pred = f0.x + f0.y + f1.x + f1.y;
            pred += __shfl_xor_sync(0xffffffffu, pred, 1);
            pred += __shfl_xor_sync(0xffffffffu, pred, 2);
            pred *= eg;
            float delta = (vv - pred) * bt;

            unsigned long long eg2 = pk2(eg, eg), d2 = pk2(delta, delta);
            unsigned long long o0 = 0ull, o1 = 0ull;
#pragma unroll
            for (int m4 = 0; m4 < 16; m4++) {
                float4 k4 = kp[m4];
                float4 q4 = qp[m4];
                unsigned long long s0 = fma2u(pk2(k4.x, k4.y), d2, mul2u(eg2, S[2 * m4]));
                unsigned long long s1 = fma2u(pk2(k4.z, k4.w), d2, mul2u(eg2, S[2 * m4 + 1]));
                S[2 * m4] = s0;
                S[2 * m4 + 1] = s1;
                o0 = fma2u(pk2(q4.x, q4.y), s0, o0);
                o1 = fma2u(pk2(q4.z, q4.w), s1, o1);
            }
            float2 g0 = up2(o0), g1 = up2(o1);
            float ov = g0.x + g0.y + g1.x + g1.y;
            ov += __shfl_xor_sync(0xffffffffu, ov, 1);
            ov += __shfl_xor_sync(0xffffffffu, ov, 2);
            if (kseg == 0)
                o[((size_t)(b * T_ + t0 + tt) * H_ + h) * DVH + s * DVS + vl] = ov;
        }
        __syncthreads();
    }
}

// ---------------- fat kernel: scan (96 CTAs) + gate GEMM (1536 CTAs) ----------------
__global__ __launch_bounds__(256, 1)
void scan_gemm(const float* __restrict__ qn, const float* __restrict__ kn,
               const float* __restrict__ vn, const float* __restrict__ gd,
               const float* __restrict__ bt, float* __restrict__ od,
               const __half* __restrict__ ah, const __half* __restrict__ al,
               const __half* __restrict__ wgh, float* __restrict__ gt) {
    extern __shared__ __align__(16) char smem[];
    if (blockIdx.x < SCAN_CTAS) {
        scan_body(qn, kn, vn, gd, bt, od, blockIdx.x, smem);
    } else {
        int gi = blockIdx.x - SCAN_CTAS;
        gemm_tile(ah, al, wgh, gt, gt, gt, VALD, VALD, VALD, VALD, VALD,
                  HID_, gi % (VALD / 128), gi / (VALD / 128), smem);
    }
}

// ---------------- fp32 -> fp16 hi/lo split (lo scaled by 2^11) ----------------
__global__ void split4(const float* __restrict__ x, __half* __restrict__ xh,
                       __half* __restrict__ xl) {
    int i4 = blockIdx.x * 256 + threadIdx.x;
    float4 v = ((const float4*)x)[i4];
    __half h0 = __float2half_rn(v.x), h1 = __float2half_rn(v.y);
    __half h2 = __float2half_rn(v.z), h3 = __float2half_rn(v.w);
    __half l0 = __float2half_rn((v.x - __half2float(h0)) * LOSCALE);
    __half l1 = __float2half_rn((v.y - __half2float(h1)) * LOSCALE);
    __half l2 = __float2half_rn((v.z - __half2float(h2)) * LOSCALE);
    __half l3 = __float2half_rn((v.w - __half2float(h3)) * LOSCALE);
    __half2* hp = (__half2*)(xh + (size_t)i4 * 4);
    __half2* lp = (__half2*)(xl + (size_t)i4 * 4);
    hp[0] = __halves2half2(h0, h1); hp[1] = __halves2half2(h2, h3);
    lp[0] = __halves2half2(l0, l1); lp[1] = __halves2half2(l2, l3);
}

// ---------------- weight transpose: W[K,N] -> Wh [N,K] fp16 (hi only) ----------------
__global__ void tsplit1(const float* __restrict__ W, __half* __restrict__ Wh, int K, int N) {
    __shared__ float tile[32][33];
    int n0 = blockIdx.x * 32, k0 = blockIdx.y * 32;
    int tx = threadIdx.x & 31, ty = threadIdx.x >> 5;   // 32x8
#pragma unroll
    for (int i = 0; i < 4; i++) {
        int k = k0 + ty + i * 8;
        tile[ty + i * 8][tx] = W[(size_t)k * N + n0 + tx];
    }
    __syncthreads();
#pragma unroll
    for (int i = 0; i < 4; i++) {
        int n = n0 + ty + i * 8;
        Wh[(size_t)n * K + k0 + tx] = __float2half_rn(tile[tx][ty + i * 8]);
    }
}

// ---------------- fused causal depthwise conv (K=4) + SiLU for q,k,v ----------------
__global__ void conv_silu_all(const float* __restrict__ xq, const float* __restrict__ xk,
                              const float* __restrict__ xv,
                              const float* __restrict__ wq, const float* __restrict__ wk,
                              const float* __restrict__ wv,
                              float* __restrict__ yq, float* __restrict__ yk,
                              float* __restrict__ yv) {
    int idx = blockIdx.x * 256 + threadIdx.x;
    const float* x; const float* w; float* y; int D;
    const int NQ = ROWS_ * KEYD;
    if (idx < NQ)           { x = xq; w = wq; y = yq; D = KEYD; }
    else if (idx < 2 * NQ)  { idx -= NQ; x = xk; w = wk; y = yk; D = KEYD; }
    else                    { idx -= 2 * NQ; x = xv; w = wv; y = yv; D = VALD; }
    int d = idx % D;
    int t = (idx / D) & (T_ - 1);
    float4 wvv = *(const float4*)(w + d * 4);
    float acc = x[idx] * wvv.w;
    if (t >= 1) acc += x[idx - D] * wvv.z;
    if (t >= 2) acc += x[idx - 2 * D] * wvv.y;
    if (t >= 3) acc += x[idx - 3 * D] * wvv.x;
    y[idx] = acc / (1.f + expf(-acc));
}

// ---------------- fused per-(b,t,h) L2 norm over 256 for q (x1/16) and k ----------------
__global__ void l2norm_qk(float* __restrict__ q, float* __restrict__ k) {
    int gw = (blockIdx.x * 256 + threadIdx.x) >> 5;
    int lane = threadIdx.x & 31;
    const int NR = ROWS_ * H_;
    float scale; float* x;
    if (gw < NR) { x = q; scale = 0.0625f; }
    else         { x = k; gw -= NR; scale = 1.0f; }
    float* row = x + (size_t)gw * DKH;
    float4 v0 = *(const float4*)(row + lane * 8);
    float4 v1 = *(const float4*)(row + lane * 8 + 4);
    float ss = v0.x * v0.x + v0.y * v0.y + v0.z * v0.z + v0.w * v0.w +
               v1.x * v1.x + v1.y * v1.y + v1.z * v1.z + v1.w * v1.w;
#pragma unroll
    for (int o = 16; o; o >>= 1) ss += __shfl_xor_sync(0xffffffffu, ss, o);
    float r = rsqrtf(ss) * scale;
    v0.x *= r; v0.y *= r; v0.z *= r; v0.w *= r;
    v1.x *= r; v1.y *= r; v1.z *= r; v1.w *= r;
    *(float4*)(row + lane * 8) = v0;
    *(float4*)(row + lane * 8 + 4) = v1;
}

// ---------------- transpose Wa/Wb (2048x6 -> 6x2048) ----------------
__global__ void transpose6(const float* __restrict__ Wa, const float* __restrict__ Wb,
                           float* __restrict__ WaT, float* __restrict__ WbT) {
    int i = blockIdx.x * 256 + threadIdx.x;
    int c = i / H_, h = i % H_;
    WaT[h * HID_ + c] = Wa[i];
    WbT[h * HID_ + c] = Wb[i];
}

// ---------------- beta / decay projection ----------------
__global__ void proj_ab(const float* __restrict__ hid, const float* __restrict__ WaT,
                        const float* __restrict__ WbT, const float* __restrict__ A_log,
                        const float* __restrict__ dt_bias,
                        float* __restrict__ gdec, float* __restrict__ beta) {
    int gw = (blockIdx.x * 256 + threadIdx.x) >> 5;
    int lane = threadIdx.x & 31;
    const float* hr = hid + (size_t)gw * HID_;
    float da0 = 0, da1 = 0, da2 = 0, da3 = 0, da4 = 0, da5 = 0;
    float db0 = 0, db1 = 0, db2 = 0, db3 = 0, db4 = 0, db5 = 0;
    for (int c = lane; c < HID_; c += 32) {
        float hv = hr[c];
        da0 += hv * WaT[0 * HID_ + c]; db0 += hv * WbT[0 * HID_ + c];
        da1 += hv * WaT[1 * HID_ + c]; db1 += hv * WbT[1 * HID_ + c];
        da2 += hv * WaT[2 * HID_ + c]; db2 += hv * WbT[2 * HID_ + c];
        da3 += hv * WaT[3 * HID_ + c]; db3 += hv * WbT[3 * HID_ + c];
        da4 += hv * WaT[4 * HID_ + c]; db4 += hv * WbT[4 * HID_ + c];
        da5 += hv * WaT[5 * HID_ + c]; db5 += hv * WbT[5 * HID_ + c];
    }
#pragma unroll
    for (int o = 16; o; o >>= 1) {
        da0 += __shfl_xor_sync(~0u, da0, o); db0 += __shfl_xor_sync(~0u, db0, o);
        da1 += __shfl_xor_sync(~0u, da1, o); db1 += __shfl_xor_sync(~0u, db1, o);
        da2 += __shfl_xor_sync(~0u, da2, o); db2 += __shfl_xor_sync(~0u, db2, o);
        da3 += __shfl_xor_sync(~0u, da3, o); db3 += __shfl_xor_sync(~0u, db3, o);
        da4 += __shfl_xor_sync(~0u, da4, o); db4 += __shfl_xor_sync(~0u, db4, o);
        da5 += __shfl_xor_sync(~0u, da5, o); db5 += __shfl_xor_sync(~0u, db5, o);
    }
    if (lane == 0) {
        float da[6] = {da0, da1, da2, da3, da4, da5};
        float db[6] = {db0, db1, db2, db3, db4, db5};
#pragma unroll
        for (int h = 0; h < 6; h++) {
            float x = da[h] + dt_bias[h];
            float sp = (x > 20.f) ? x : log1pf(expf(x));
            gdec[gw * H_ + h] = -expf(A_log[h]) * sp;
            beta[gw * H_ + h] = 1.f / (1.f + expf(-db[h]));
        }
    }
}

// ---------------- RMSNorm * weight * silu(gate) -> fp16 hi/lo split ----------------
__global__ void norm_gate(const float* __restrict__ o, const float* __restrict__ gate,
                          const float* __restrict__ nw,
                          __half* __restrict__ yh, __half* __restrict__ yl) {
    int gw = (blockIdx.x * 256 + threadIdx.x) >> 5;
    int lane = threadIdx.x & 31;
    size_t base = (size_t)gw * DVH;
    float4 v[4];
    float ss = 0.f;
#pragma unroll
    for (int i = 0; i < 4; i++) {
        v[i] = *(const float4*)(o + base + (lane + i * 32) * 4);
        ss += v[i].x * v[i].x + v[i].y * v[i].y + v[i].z * v[i].z + v[i].w * v[i].w;
    }
#pragma unroll
    for (int off = 16; off; off >>= 1) ss += __shfl_xor_sync(0xffffffffu, ss, off);
    float r = rsqrtf(ss * (1.f / 512.f) + 1e-5f);
#pragma unroll
    for (int i = 0; i < 4; i++) {
        int d4 = (lane + i * 32) * 4;
        float4 gt = *(const float4*)(gate + base + d4);
        float4 w = *(const float4*)(nw + d4);
        float o0 = v[i].x * r * w.x * (gt.x / (1.f + expf(-gt.x)));
        float o1 = v[i].y * r * w.y * (gt.y / (1.f + expf(-gt.y)));
        float o2 = v[i].z * r * w.z * (gt.z / (1.f + expf(-gt.z)));
        float o3 = v[i].w * r * w.w * (gt.w / (1.f + expf(-gt.w)));
        __half h0 = __float2half_rn(o0), h1 = __float2half_rn(o1);
        __half h2 = __float2half_rn(o2), h3 = __float2half_rn(o3);
        __half2* hp = (__half2*)(yh + base + d4);
        __half2* lp = (__half2*)(yl + base + d4);
        hp[0] = __halves2half2(h0, h1);
        hp[1] = __halves2half2(h2, h3);
        lp[0] = __halves2half2(__float2half_rn((o0 - __half2float(h0)) * LOSCALE),
                               __float2half_rn((o1 - __half2float(h1)) * LOSCALE));
        lp[1] = __halves2half2(__float2half_rn((o2 - __half2float(h2)) * LOSCALE),
                               __float2half_rn((o3 - __half2float(h3)) * LOSCALE));
    }
}

// ---------------- launch ----------------
extern "C" void kernel_launch(void* const* d_in, const int* in_sizes, int n_in,
                              void* d_out, int out_size) {
    const float* hid  = (const float*)d_in[0];
    const float* Wq   = (const float*)d_in[1];
    const float* Wk   = (const float*)d_in[2];
    const float* Wv   = (const float*)d_in[3];
    const float* Wa   = (const float*)d_in[4];
    const float* Wb   = (const float*)d_in[5];
    const float* Wg   = (const float*)d_in[6];
    const float* Wo   = (const float*)d_in[7];
    const float* cwq  = (const float*)d_in[8];
    const float* cwk  = (const float*)d_in[9];
    const float* cwv  = (const float*)d_in[10];
    const float* Alog = (const float*)d_in[11];
    const float* dtb  = (const float*)d_in[12];
    const float* nw   = (const float*)d_in[13];

    float *xq, *xk, *xv, *gt, *qn, *kn, *vn, *od, *gd, *bt, *wat, *wbt;
    __half *ah, *al, *yh, *yl, *wqkvh, *wgh, *woh;
    cudaGetSymbolAddress((void**)&xq, g_xq);
    cudaGetSymbolAddress((void**)&xk, g_xk);
    cudaGetSymbolAddress((void**)&xv, g_xv);
    cudaGetSymbolAddress((void**)&gt, g_gt);
    cudaGetSymbolAddress((void**)&qn, g_qn);
    cudaGetSymbolAddress((void**)&kn, g_kn);
    cudaGetSymbolAddress((void**)&vn, g_vn);
    cudaGetSymbolAddress((void**)&od, g_od);
    cudaGetSymbolAddress((void**)&gd, g_gd);
    cudaGetSymbolAddress((void**)&bt, g_bt);
    cudaGetSymbolAddress((void**)&wat, g_wat);
    cudaGetSymbolAddress((void**)&wbt, g_wbt);
    cudaGetSymbolAddress((void**)&ah, g_ah);
    cudaGetSymbolAddress((void**)&al, g_al);
    cudaGetSymbolAddress((void**)&yh, g_yh);
    cudaGetSymbolAddress((void**)&yl, g_yl);
    cudaGetSymbolAddress((void**)&wqkvh, g_wqkvh);
    cudaGetSymbolAddress((void**)&wgh, g_wgh);
    cudaGetSymbolAddress((void**)&woh, g_woh);

    cudaFuncSetAttribute(gemm_hx2, cudaFuncAttributeMaxDynamicSharedMemorySize, GEMM_SMEM);
    cudaFuncSetAttribute(scan_gemm, cudaFuncAttributeMaxDynamicSharedMemorySize, GEMM_SMEM);

    // fp16 prep: activations (hi+lo) + weights (hi only, transposed to [N,K])
    split4<<<(ROWS_ * HID_ / 4) / 256, 256>>>(hid, ah, al);
    tsplit1<<<dim3(KEYD / 32, HID_ / 32), 256>>>(Wq, wqkvh, HID_, KEYD);
    tsplit1<<<dim3(KEYD / 32, HID_ / 32), 256>>>(Wk, wqkvh + (size_t)KEYD * HID_, HID_, KEYD);
    tsplit1<<<dim3(VALD / 32, HID_ / 32), 256>>>(Wv, wqkvh + (size_t)2 * KEYD * HID_, HID_, VALD);
    tsplit1<<<dim3(VALD / 32, HID_ / 32), 256>>>(Wg, wgh, HID_, VALD);
    tsplit1<<<dim3(HID_ / 32, VALD / 32), 256>>>(Wo, woh, VALD, HID_);

    // beta / decay (before the fat kernel)
    transpose6<<<(H_ * HID_) / 256, 256>>>(Wa, Wb, wat, wbt);
    proj_ab<<<(ROWS_ * 32) / 256, 256>>>(hid, wat, wbt, Alog, dtb, gd, bt);

    // fused Q|K|V projection (N = 6144, 3-way routed epilogue)
    gemm_hx2<<<dim3((2 * KEYD + VALD) / 128, ROWS_ / 128), 256, GEMM_SMEM>>>(
        ah, al, wqkvh, xq, xk, xv, KEYD, 2 * KEYD, KEYD, KEYD, VALD, HID_);

    // fused conv + silu (q,k,v in one launch)
    conv_silu_all<<<(ROWS_ * (2 * KEYD + VALD)) / 256, 256>>>(
        xq, xk, xv, cwq, cwk, cwv, qn, kn, vn);

    // fused l2 norms (q scaled by 1/16, k unit)
    l2norm_qk<<<(2 * ROWS_ * H_ * 32) / 256, 256>>>(qn, kn);

    // fat kernel: scan on 96 CTAs + gate GEMM (Wg) backfilling idle SMs
    scan_gemm<<<SCAN_CTAS + (VALD / 128) * (ROWS_ / 128), 256, GEMM_SMEM>>>(
        qn, kn, vn, gd, bt, od, ah, al, wgh, gt);

    // rmsnorm * weight * silu(gate) -> fp16 hi/lo
    norm_gate<<<(ROWS_ * H_ * 32) / 256, 256>>>(od, gt, nw, yh, yl);

    // output projection -> d_out
    gemm_hx2<<<dim3(HID_ / 128, ROWS_ / 128), 256, GEMM_SMEM>>>(
        yh, yl, woh, (float*)d_out, (float*)d_out, (float*)d_out,
        HID_, HID_, HID_, HID_, HID_, VALD);
}

// round 13
// speedup vs baseline: 1.0918x; 1.0462x over previous
#include <cuda_runtime.h>
#include <cuda_fp16.h>
#include <math.h>
#include <stdint.h>

// ---------------- problem constants ----------------
#define B_ 2
#define T_ 4096
#define HID_ 2048
#define H_ 6
#define DKH 256
#define DVH 512
#define KEYD 1536
#define VALD 3072
#define ROWS_ (B_ * T_)          // 8192
#define DVS 64                   // dv slice per scan CTA
#define NSL 8                    // 512/64
#define TOKB 8                   // tokens staged per scan round
#define LOSCALE 2048.0f
#define INVLOSCALE (1.0f / 2048.0f)
#define SCAN_CTAS (B_ * H_ * NSL)   // 96

// ---------------- scratch (device globals; no allocation allowed) ----------------
__device__ float g_xq[ROWS_ * KEYD];
__device__ float g_xk[ROWS_ * KEYD];
__device__ float g_xv[ROWS_ * VALD];
__device__ float g_gt[ROWS_ * VALD];
__device__ float g_qn[ROWS_ * KEYD];
__device__ float g_kn[ROWS_ * KEYD];
__device__ float g_vn[ROWS_ * VALD];
__device__ float g_od[ROWS_ * VALD];
__device__ float g_gd[ROWS_ * H_];
__device__ float g_bt[ROWS_ * H_];
__device__ float g_wat[H_ * HID_];
__device__ float g_wbt[H_ * HID_];
// fp16 buffers (activation lo scaled by 2^11); weights hi-only
__device__ __half g_ah[ROWS_ * HID_];
__device__ __half g_al[ROWS_ * HID_];
__device__ __half g_yh[ROWS_ * VALD];
__device__ __half g_wqkvh[(2 * KEYD + VALD) * HID_];  // Wq | Wk | Wv rows, [N,K]
__device__ __half g_wgh[VALD * HID_];
__device__ __half g_woh[HID_ * VALD];

// ---------------- packed f32x2 helpers ----------------
__device__ __forceinline__ unsigned long long pk2(float x, float y) {
    unsigned long long r;
    asm("mov.b64 %0, {%1, %2};" : "=l"(r) : "f"(x), "f"(y));
    return r;
}
__device__ __forceinline__ float2 up2(unsigned long long v) {
    float2 r;
    asm("mov.b64 {%0, %1}, %2;" : "=f"(r.x), "=f"(r.y) : "l"(v));
    return r;
}
__device__ __forceinline__ unsigned long long fma2u(unsigned long long a, unsigned long long b, unsigned long long c) {
    unsigned long long d;
    asm("fma.rn.f32x2 %0, %1, %2, %3;" : "=l"(d) : "l"(a), "l"(b), "l"(c));
    return d;
}
__device__ __forceinline__ unsigned long long mul2u(unsigned long long a, unsigned long long b) {
    unsigned long long d;
    asm("mul.rn.f32x2 %0, %1, %2;" : "=l"(d) : "l"(a), "l"(b));
    return d;
}

// ---------------- mma.sync / ldmatrix / cp.async helpers ----------------
__device__ __forceinline__ uint32_t smem_u32(const void* p) {
    uint32_t a;
    asm("{ .reg .u64 t; cvta.to.shared.u64 t, %1; cvt.u32.u64 %0, t; }" : "=r"(a) : "l"(p));
    return a;
}
__device__ __forceinline__ void ldm_x4(uint32_t* r, uint32_t addr) {
    asm volatile("ldmatrix.sync.aligned.m8n8.x4.shared.b16 {%0,%1,%2,%3}, [%4];"
                 : "=r"(r[0]), "=r"(r[1]), "=r"(r[2]), "=r"(r[3]) : "r"(addr));
}
__device__ __forceinline__ void mma_hf32(float* c, const uint32_t* a, const uint32_t* b) {
    asm volatile("mma.sync.aligned.m16n8k16.row.col.f32.f16.f16.f32 "
                 "{%0,%1,%2,%3}, {%4,%5,%6,%7}, {%8,%9}, {%0,%1,%2,%3};"
                 : "+f"(c[0]), "+f"(c[1]), "+f"(c[2]), "+f"(c[3])
                 : "r"(a[0]), "r"(a[1]), "r"(a[2]), "r"(a[3]), "r"(b[0]), "r"(b[1]));
}
__device__ __forceinline__ void mma_hf16(uint32_t* c, const uint32_t* a, const uint32_t* b) {
    asm volatile("mma.sync.aligned.m16n8k16.row.col.f16.f16.f16.f16 "
                 "{%0,%1}, {%2,%3,%4,%5}, {%6,%7}, {%0,%1};"
                 : "+r"(c[0]), "+r"(c[1])
                 : "r"(a[0]), "r"(a[1]), "r"(a[2]), "r"(a[3]), "r"(b[0]), "r"(b[1]));
}
__device__ __forceinline__ void cp16(uint32_t sm, const void* gp) {
    asm volatile("cp.async.cg.shared.global [%0], [%1], 16;" :: "r"(sm), "l"(gp));
}
#define CP_COMMIT() asm volatile("cp.async.commit_group;" ::: "memory")
#define CP_WAIT0()  asm volatile("cp.async.wait_group 0;" ::: "memory")

// ---------------- fp16 HMMA GEMM tile, templated on precision ----------------
// USE_LO=true : C = Ah*Bh (f32 acc) + 2^-11*(Al'*Bh) (f16 acc), 3 smem tiles.
// USE_LO=false: C = Ah*Bh (f32 acc) only, 2 smem tiles (single-product fp16).
// CTA 128x128, 256 threads, warp tile 64x32, K-chunk 64, 2-stage cp.async (R8).
// SMEM rows padded to 72 halves (144B) -> conflict-free ldmatrix.
// 3-way column routing: [0,split1)->C0/str0, [split1,split2)->C1/str1, rest->C2/str2.
#define GTILE 18432            // 128 rows * 144 B
#define GEMM_SMEM3 110592      // 2 stages * 3 tiles
#define GEMM_SMEM2 73728       // 2 stages * 2 tiles

template <bool USE_LO>
__device__ __forceinline__ void gemm_tile(
    const __half* __restrict__ Ahi, const __half* __restrict__ Alo,
    const __half* __restrict__ Bhi,
    float* __restrict__ C0, float* __restrict__ C1, float* __restrict__ C2,
    int split1, int split2, int str0, int str1, int str2,
    int K, int bx, int by, char* smem) {
    constexpr int NT = USE_LO ? 3 : 2;        // tiles per stage (A[,Alo],B)
    constexpr int GBUF = NT * GTILE;
    const uint32_t sbase = smem_u32(smem);
    const int tid = threadIdx.x, lane = tid & 31, wid = tid >> 5;
    const int wm = wid & 1, wn = wid >> 1;    // 2 x 4 warp grid
    const int brow = by * 128, bcol = bx * 128;

    const __half* srcs[NT];
    int row0[NT];
    srcs[0] = Ahi; row0[0] = brow;
    if constexpr (USE_LO) { srcs[1] = Alo; row0[1] = brow; srcs[2] = Bhi; row0[2] = bcol; }
    else                  { srcs[1] = Bhi; row0[1] = bcol; }

    float accF[4][4][4];
    uint32_t accH[4][4][2];
#pragma unroll
    for (int i = 0; i < 4; i++)
#pragma unroll
        for (int j = 0; j < 4; j++) {
#pragma unroll
            for (int l = 0; l < 4; l++) accF[i][j][l] = 0.f;
            accH[i][j][0] = 0u; accH[i][j][1] = 0u;
        }

    const int r_ = tid >> 3, c8_ = (tid & 7) * 8;

    // prologue: chunk 0 -> buf 0
#pragma unroll
    for (int ts = 0; ts < NT; ts++) {
        const __half* sp = srcs[ts] + (size_t)(row0[ts] + r_) * K + c8_;
        uint32_t tb = sbase + ts * GTILE + r_ * 144 + c8_ * 2;
#pragma unroll
        for (int i = 0; i < 4; i++)
            cp16(tb + i * 32 * 144, sp + (size_t)(i * 32) * K);
    }
    CP_COMMIT();
    CP_WAIT0();
    __syncthreads();

    const int numT = K >> 6;
    const uint32_t a_lane = (lane & 15) * 144 + (lane >> 4) * 16;
    const uint32_t b_lane4 = ((lane & 7) + (lane >> 4) * 8) * 144 + ((lane >> 3) & 1) * 16;

    for (int c = 0; c < numT; c++) {
        const int b = c & 1;
        if (c + 1 < numT) {
            const int kc = (c + 1) << 6, nb = b ^ 1;
#pragma unroll
            for (int ts = 0; ts < NT; ts++) {
                const __half* sp = srcs[ts] + (size_t)(row0[ts] + r_) * K + kc + c8_;
                uint32_t tb = sbase + nb * GBUF + ts * GTILE + r_ * 144 + c8_ * 2;
#pragma unroll
                for (int i = 0; i < 4; i++)
                    cp16(tb + i * 32 * 144, sp + (size_t)(i * 32) * K);
            }
            CP_COMMIT();
        }
        const uint32_t aH = sbase + b * GBUF + wm * 64 * 144;
        const uint32_t aL = aH + GTILE;     // only valid if USE_LO
        const uint32_t bH = sbase + b * GBUF + (NT - 1) * GTILE + wn * 32 * 144;
#pragma unroll
        for (int ks = 0; ks < 4; ks++) {
            const uint32_t acol = ks * 32 + a_lane;
            const uint32_t bcol2 = ks * 32 + b_lane4;
            uint32_t fAH[4][4], fAL[4][4], fBH[4][2];
#pragma unroll
            for (int mt = 0; mt < 4; mt++) {
                ldm_x4(fAH[mt], aH + mt * 16 * 144 + acol);
                if constexpr (USE_LO) ldm_x4(fAL[mt], aL + mt * 16 * 144 + acol);
            }
#pragma unroll
            for (int p = 0; p < 2; p++) {
                uint32_t r4[4];
                ldm_x4(r4, bH + p * 16 * 144 + bcol2);
                fBH[2 * p][0] = r4[0]; fBH[2 * p][1] = r4[1];
                fBH[2 * p + 1][0] = r4[2]; fBH[2 * p + 1][1] = r4[3];
            }
#pragma unroll
            for (int mt = 0; mt < 4; mt++)
#pragma unroll
                for (int nt = 0; nt < 4; nt++) {
                    mma_hf32(accF[mt][nt], fAH[mt], fBH[nt]);
                    if constexpr (USE_LO) mma_hf16(accH[mt][nt], fAL[mt], fBH[nt]);
                }
        }
        CP_WAIT0();
        __syncthreads();
    }

    // epilogue: merge + 3-way route
    float* Cp; int ccol0, strN;
    if (bcol < split1)      { Cp = C0; ccol0 = bcol;          strN = str0; }
    else if (bcol < split2) { Cp = C1; ccol0 = bcol - split1; strN = str1; }
    else                    { Cp = C2; ccol0 = bcol - split2; strN = str2; }
    const int r0 = lane >> 2, cc = (lane & 3) * 2;
#pragma unroll
    for (int mt = 0; mt < 4; mt++)
#pragma unroll
        for (int nt = 0; nt < 4; nt++) {
            size_t base = (size_t)(brow + wm * 64 + mt * 16 + r0) * strN + ccol0 + wn * 32 + nt * 8 + cc;
            if constexpr (USE_LO) {
                float2 lo01 = __half22float2(*(__half2*)&accH[mt][nt][0]);
                float2 lo23 = __half22float2(*(__half2*)&accH[mt][nt][1]);
                *(float2*)&Cp[base] = make_float2(accF[mt][nt][0] + lo01.x * INVLOSCALE,
                                                  accF[mt][nt][1] + lo01.y * INVLOSCALE);
                *(float2*)&Cp[base + 8 * (size_t)strN] = make_float2(accF[mt][nt][2] + lo23.x * INVLOSCALE,
                                                                     accF[mt][nt][3] + lo23.y * INVLOSCALE);
            } else {
                *(float2*)&Cp[base] = make_float2(accF[mt][nt][0], accF[mt][nt][1]);
                *(float2*)&Cp[base + 8 * (size_t)strN] = make_float2(accF[mt][nt][2], accF[mt][nt][3]);
            }
        }
}

__global__ __launch_bounds__(256, 1)
void gemm_hilo(const __half* __restrict__ Ahi, const __half* __restrict__ Alo,
               const __half* __restrict__ Bhi,
               float* C0, float* C1, float* C2,
               int split1, int split2, int str0, int str1, int str2, int K) {
    extern __shared__ __align__(16) char smem[];
    gemm_tile<true>(Ahi, Alo, Bhi, C0, C1, C2, split1, split2, str0, str1, str2,
                    K, blockIdx.x, blockIdx.y, smem);
}

__global__ __launch_bounds__(256, 1)
void gemm_hi(const __half* __restrict__ Ahi, const __half* __restrict__ Bhi,
             float* C0, int strN, int K) {
    extern __shared__ __align__(16) char smem[];
    gemm_tile<false>(Ahi, Ahi, Bhi, C0, C0, C0, strN, strN, strN, strN, strN,
                     K, blockIdx.x, blockIdx.y, smem);
}

// ---------------- gated delta rule scan, device body (R8 known-good) ----------------
__device__ __forceinline__ void scan_body(
    const float* __restrict__ q, const float* __restrict__ k,
    const float* __restrict__ v, const float* __restrict__ g,
    const float* __restrict__ beta, float* __restrict__ o,
    int bi, char* smemc) {
    float (*ks)[272] = (float(*)[272])(smemc);
    float (*qs)[272] = (float(*)[272])(smemc + 8704);
    float (*vs)[DVS] = (float(*)[DVS])(smemc + 17408);
    float* egs = (float*)(smemc + 19456);
    float* bts = (float*)(smemc + 19488);

    const int s = bi & 7;
    const int h = (bi >> 3) % H_;
    const int b = bi / (H_ * NSL);
    const int tid = threadIdx.x;
    const int vl = tid >> 2, kseg = tid & 3;
    const int sidx = (tid >> 6) * 68 + (tid & 63);

    unsigned long long S[32];
#pragma unroll
    for (int m = 0; m < 32; m++) S[m] = 0ull;

    for (int t0 = 0; t0 < T_; t0 += TOKB) {
#pragma unroll
        for (int tt = 0; tt < TOKB; tt++) {
            size_t base = ((size_t)(b * T_ + t0 + tt) * H_ + h) * DKH;
            ks[tt][sidx] = k[base + tid];
            qs[tt][sidx] = q[base + tid];
        }
#pragma unroll
        for (int i = 0; i < 2; i++) {
            int ee = i * 256 + tid;
            int tt = ee >> 6, vle = ee & 63;
            vs[tt][vle] = v[((size_t)(b * T_ + t0 + tt) * H_ + h) * DVH + s * DVS + vle];
        }
        if (tid < TOKB) {
            size_t gi = (size_t)(b * T_ + t0 + tid) * H_ + h;
            egs[tid] = expf(g[gi]);
            bts[tid] = beta[gi];
        }
        __syncthreads();

#pragma unroll 1
        for (int tt = 0; tt < TOKB; tt++) {
            float eg = egs[tt], bt = bts[tt], vv = vs[tt][vl];
            const float4* kp = (const float4*)&ks[tt][kseg * 68];
            const float4* qp = (const float4*)&qs[tt][kseg * 68];

            unsigned long long a0 = 0ull, a1 = 0ull;
#pragma unroll
            for (int m4 = 0; m4 < 16; m4++) {
                float4 k4 = kp[m4];
                a0 = fma2u(pk2(k4.x, k4.y), S[2 * m4], a0);
                a1 = fma2u(pk2(k4.z, k4.w), S[2 * m4 + 1], a1);
            }
            float2 f0 = up2(a0), f1 = up2(a1);
            float pred = f0.x + f0.y + f1.x + f1.y;
            pred += __shfl_xor_sync(0xffffffffu, pred, 1);
            pred += __shfl_xor_sync(0xffffffffu, pred, 2);
            pred *= eg;
            float delta = (vv - pred) * bt;

            unsigned long long eg2 = pk2(eg, eg), d2 = pk2(delta, delta);
            unsigned long long o0 = 0ull, o1 = 0ull;
#pragma unroll
            for (int m4 = 0; m4 < 16; m4++) {
                float4 k4 = kp[m4];
                float4 q4 = qp[m4];
                unsigned long long s0 = fma2u(pk2(k4.x, k4.y), d2, mul2u(eg2, S[2 * m4]));
                unsigned long long s1 = fma2u(pk2(k4.z, k4.w), d2, mul2u(eg2, S[2 * m4 + 1]));
                S[2 * m4] = s0;
                S[2 * m4 + 1] = s1;
                o0 = fma2u(pk2(q4.x, q4.y), s0, o0);
                o1 = fma2u(pk2(q4.z, q4.w), s1, o1);
            }
            float2 g0 = up2(o0), g1 = up2(o1);
            float ov = g0.x + g0.y + g1.x + g1.y;
            ov += __shfl_xor_sync(0xffffffffu, ov, 1);
            ov += __shfl_xor_sync(0xffffffffu, ov, 2);
            if (kseg == 0)
                o[((size_t)(b * T_ + t0 + tt) * H_ + h) * DVH + s * DVS + vl] = ov;
        }
        __syncthreads();
    }
}

// ---------------- fat kernel: scan (96 CTAs) + single-product gate GEMM ----------------
__global__ __launch_bounds__(256, 1)
void scan_gemm(const float* __restrict__ qn, const float* __restrict__ kn,
               const float* __restrict__ vn, const float* __restrict__ gd,
               const float* __restrict__ bt, float* __restrict__ od,
               const __half* __restrict__ ah, const __half* __restrict__ wgh,
               float* __restrict__ gt) {
    extern __shared__ __align__(16) char smem[];
    if (blockIdx.x < SCAN_CTAS) {
        scan_body(qn, kn, vn, gd, bt, od, blockIdx.x, smem);
    } else {
        int gi = blockIdx.x - SCAN_CTAS;
        gemm_tile<false>(ah, ah, wgh, gt, gt, gt, VALD, VALD, VALD, VALD, VALD,
                         HID_, gi % (VALD / 128), gi / (VALD / 128), smem);
    }
}

// ---------------- fp32 -> fp16 hi/lo split (lo scaled by 2^11) ----------------
__global__ void split4(const float* __restrict__ x, __half* __restrict__ xh,
                       __half* __restrict__ xl) {
    int i4 = blockIdx.x * 256 + threadIdx.x;
    float4 v = ((const float4*)x)[i4];
    __half h0 = __float2half_rn(v.x), h1 = __float2half_rn(v.y);
    __half h2 = __float2half_rn(v.z), h3 = __float2half_rn(v.w);
    __half l0 = __float2half_rn((v.x - __half2float(h0)) * LOSCALE);
    __half l1 = __float2half_rn((v.y - __half2float(h1)) * LOSCALE);
    __half l2 = __float2half_rn((v.z - __half2float(h2)) * LOSCALE);
    __half l3 = __float2half_rn((v.w - __half2float(h3)) * LOSCALE);
    __half2* hp = (__half2*)(xh + (size_t)i4 * 4);
    __half2* lp = (__half2*)(xl + (size_t)i4 * 4);
    hp[0] = __halves2half2(h0, h1); hp[1] = __halves2half2(h2, h3);
    lp[0] = __halves2half2(l0, l1); lp[1] = __halves2half2(l2, l3);
}

// ---------------- fp32 -> fp16 (hi only, vectorized) ----------------
__global__ void cvt4(const float* __restrict__ x, __half* __restrict__ xh) {
    int i4 = blockIdx.x * 256 + threadIdx.x;
    float4 v = ((const float4*)x)[i4];
    __half2* hp = (__half2*)(xh + (size_t)i4 * 4);
    hp[0] = __halves2half2(__float2half_rn(v.x), __float2half_rn(v.y));
    hp[1] = __halves2half2(__float2half_rn(v.z), __float2half_rn(v.w));
}

// ---------------- weight transpose: W[K,N] -> Wh [N,K] fp16 (hi only) ----------------
__global__ void tsplit1(const float* __restrict__ W, __half* __restrict__ Wh, int K, int N) {
    __shared__ float tile[32][33];
    int n0 = blockIdx.x * 32, k0 = blockIdx.y * 32;
    int tx = threadIdx.x & 31, ty = threadIdx.x >> 5;   // 32x8
#pragma unroll
    for (int i = 0; i < 4; i++) {
        int k = k0 + ty + i * 8;
        tile[ty + i * 8][tx] = W[(size_t)k * N + n0 + tx];
    }
    __syncthreads();
#pragma unroll
    for (int i = 0; i < 4; i++) {
        int n = n0 + ty + i * 8;
        Wh[(size_t)n * K + k0 + tx] = __float2half_rn(tile[tx][ty + i * 8]);
    }
}

// ---------------- fused causal depthwise conv (K=4) + SiLU for q,k,v ----------------
__global__ void conv_silu_all(const float* __restrict__ xq, const float* __restrict__ xk,
                              const float* __restrict__ xv,
                              const float* __restrict__ wq, const float* __restrict__ wk,
                              const float* __restrict__ wv,
                              float* __restrict__ yq, float* __restrict__ yk,
                              float* __restrict__ yv) {
    int idx = blockIdx.x * 256 + threadIdx.x;
    const float* x; const float* w; float* y; int D;
    const int NQ = ROWS_ * KEYD;
    if (idx < NQ)           { x = xq; w = wq; y = yq; D = KEYD; }
    else if (idx < 2 * NQ)  { idx -= NQ; x = xk; w = wk; y = yk; D = KEYD; }
    else                    { idx -= 2 * NQ; x = xv; w = wv; y = yv; D = VALD; }
    int d = idx % D;
    int t = (idx / D) & (T_ - 1);
    float4 wvv = *(const float4*)(w + d * 4);
    float acc = x[idx] * wvv.w;
    if (t >= 1) acc += x[idx - D] * wvv.z;
    if (t >= 2) acc += x[idx - 2 * D] * wvv.y;
    if (t >= 3) acc += x[idx - 3 * D] * wvv.x;
    y[idx] = acc / (1.f + expf(-acc));
}

// ---------------- fused per-(b,t,h) L2 norm over 256 for q (x1/16) and k ----------------
__global__ void l2norm_qk(float* __restrict__ q, float* __restrict__ k) {
    int gw = (blockIdx.x * 256 + threadIdx.x) >> 5;
    int lane = threadIdx.x & 31;
    const int NR = ROWS_ * H_;
    float scale; float* x;
    if (gw < NR) { x = q; scale = 0.0625f; }
    else         { x = k; gw -= NR; scale = 1.0f; }
    float* row = x + (size_t)gw * DKH;
    float4 v0 = *(const float4*)(row + lane * 8);
    float4 v1 = *(const float4*)(row + lane * 8 + 4);
    float ss = v0.x * v0.x + v0.y * v0.y + v0.z * v0.z + v0.w * v0.w +
               v1.x * v1.x + v1.y * v1.y + v1.z * v1.z + v1.w * v1.w;
#pragma unroll
    for (int o = 16; o; o >>= 1) ss += __shfl_xor_sync(0xffffffffu, ss, o);
    float r = rsqrtf(ss) * scale;
    v0.x *= r; v0.y *= r; v0.z *= r; v0.w *= r;
    v1.x *= r; v1.y *= r; v1.z *= r; v1.w *= r;
    *(float4*)(row + lane * 8) = v0;
    *(float4*)(row + lane * 8 + 4) = v1;
}

// ---------------- transpose Wa/Wb (2048x6 -> 6x2048) ----------------
__global__ void transpose6(const float* __restrict__ Wa, const float* __restrict__ Wb,
                           float* __restrict__ WaT, float* __restrict__ WbT) {
    int i = blockIdx.x * 256 + threadIdx.x;
    int c = i / H_, h = i % H_;
    WaT[h * HID_ + c] = Wa[i];
    WbT[h * HID_ + c] = Wb[i];
}

// ---------------- beta / decay projection ----------------
__global__ void proj_ab(const float* __restrict__ hid, const float* __restrict__ WaT,
                        const float* __restrict__ WbT, const float* __restrict__ A_log,
                        const float* __restrict__ dt_bias,
                        float* __restrict__ gdec, float* __restrict__ beta) {
    int gw = (blockIdx.x * 256 + threadIdx.x) >> 5;
    int lane = threadIdx.x & 31;
    const float* hr = hid + (size_t)gw * HID_;
    float da0 = 0, da1 = 0, da2 = 0, da3 = 0, da4 = 0, da5 = 0;
    float db0 = 0, db1 = 0, db2 = 0, db3 = 0, db4 = 0, db5 = 0;
    for (int c = lane; c < HID_; c += 32) {
        float hv = hr[c];
        da0 += hv * WaT[0 * HID_ + c]; db0 += hv * WbT[0 * HID_ + c];
        da1 += hv * WaT[1 * HID_ + c]; db1 += hv * WbT[1 * HID_ + c];
        da2 += hv * WaT[2 * HID_ + c]; db2 += hv * WbT[2 * HID_ + c];
        da3 += hv * WaT[3 * HID_ + c]; db3 += hv * WbT[3 * HID_ + c];
        da4 += hv * WaT[4 * HID_ + c]; db4 += hv * WbT[4 * HID_ + c];
        da5 += hv * WaT[5 * HID_ + c]; db5 += hv * WbT[5 * HID_ + c];
    }
#pragma unroll
    for (int o = 16; o; o >>= 1) {
        da0 += __shfl_xor_sync(~0u, da0, o); db0 += __shfl_xor_sync(~0u, db0, o);
        da1 += __shfl_xor_sync(~0u, da1, o); db1 += __shfl_xor_sync(~0u, db1, o);
        da2 += __shfl_xor_sync(~0u, da2, o); db2 += __shfl_xor_sync(~0u, db2, o);
        da3 += __shfl_xor_sync(~0u, da3, o); db3 += __shfl_xor_sync(~0u, db3, o);
        da4 += __shfl_xor_sync(~0u, da4, o); db4 += __shfl_xor_sync(~0u, db4, o);
        da5 += __shfl_xor_sync(~0u, da5, o); db5 += __shfl_xor_sync(~0u, db5, o);
    }
    if (lane == 0) {
        float da[6] = {da0, da1, da2, da3, da4, da5};
        float db[6] = {db0, db1, db2, db3, db4, db5};
#pragma unroll
        for (int h = 0; h < 6; h++) {
            float x = da[h] + dt_bias[h];
            float sp = (x > 20.f) ? x : log1pf(expf(x));
            gdec[gw * H_ + h] = -expf(A_log[h]) * sp;
            beta[gw * H_ + h] = 1.f / (1.f + expf(-db[h]));
        }
    }
}

// ---------------- RMSNorm * weight * silu(gate) -> fp16 (hi only) ----------------
__global__ void norm_gate(const float* __restrict__ o, const float* __restrict__ gate,
                          const float* __restrict__ nw, __half* __restrict__ yh) {
    int gw = (blockIdx.x * 256 + threadIdx.x) >> 5;
    int lane = threadIdx.x & 31;
    size_t base = (size_t)gw * DVH;
    float4 v[4];
    float ss = 0.f;
#pragma unroll
    for (int i = 0; i < 4; i++) {
        v[i] = *(const float4*)(o + base + (lane + i * 32) * 4);
        ss += v[i].x * v[i].x + v[i].y * v[i].y + v[i].z * v[i].z + v[i].w * v[i].w;
    }
#pragma unroll
    for (int off = 16; off; off >>= 1) ss += __shfl_xor_sync(0xffffffffu, ss, off);
    float r = rsqrtf(ss * (1.f / 512.f) + 1e-5f);
#pragma unroll
    for (int i = 0; i < 4; i++) {
        int d4 = (lane + i * 32) * 4;
        float4 gt = *(const float4*)(gate + base + d4);
        float4 w = *(const float4*)(nw + d4);
        float o0 = v[i].x * r * w.x * (gt.x / (1.f + expf(-gt.x)));
        float o1 = v[i].y * r * w.y * (gt.y / (1.f + expf(-gt.y)));
        float o2 = v[i].z * r * w.z * (gt.z / (1.f + expf(-gt.z)));
        float o3 = v[i].w * r * w.w * (gt.w / (1.f + expf(-gt.w)));
        __half2* hp = (__half2*)(yh + base + d4);
        hp[0] = __halves2half2(__float2half_rn(o0), __float2half_rn(o1));
        hp[1] = __halves2half2(__float2half_rn(o2), __float2half_rn(o3));
    }
}

// ---------------- launch ----------------
extern "C" void kernel_launch(void* const* d_in, const int* in_sizes, int n_in,
                              void* d_out, int out_size) {
    const float* hid  = (const float*)d_in[0];
    const float* Wq   = (const float*)d_in[1];
    const float* Wk   = (const float*)d_in[2];
    const float* Wv   = (const float*)d_in[3];
    const float* Wa   = (const float*)d_in[4];
    const float* Wb   = (const float*)d_in[5];
    const float* Wg   = (const float*)d_in[6];
    const float* Wo   = (const float*)d_in[7];
    const float* cwq  = (const float*)d_in[8];
    const float* cwk  = (const float*)d_in[9];
    const float* cwv  = (const float*)d_in[10];
    const float* Alog = (const float*)d_in[11];
    const float* dtb  = (const float*)d_in[12];
    const float* nw   = (const float*)d_in[13];

    float *xq, *xk, *xv, *gt, *qn, *kn, *vn, *od, *gd, *bt, *wat, *wbt;
    __half *ah, *al, *yh, *wqkvh, *wgh, *woh;
    cudaGetSymbolAddress((void**)&xq, g_xq);
    cudaGetSymbolAddress((void**)&xk, g_xk);
    cudaGetSymbolAddress((void**)&xv, g_xv);
    cudaGetSymbolAddress((void**)&gt, g_gt);
    cudaGetSymbolAddress((void**)&qn, g_qn);
    cudaGetSymbolAddress((void**)&kn, g_kn);
    cudaGetSymbolAddress((void**)&vn, g_vn);
    cudaGetSymbolAddress((void**)&od, g_od);
    cudaGetSymbolAddress((void**)&gd, g_gd);
    cudaGetSymbolAddress((void**)&bt, g_bt);
    cudaGetSymbolAddress((void**)&wat, g_wat);
    cudaGetSymbolAddress((void**)&wbt, g_wbt);
    cudaGetSymbolAddress((void**)&ah, g_ah);
    cudaGetSymbolAddress((void**)&al, g_al);
    cudaGetSymbolAddress((void**)&yh, g_yh);
    cudaGetSymbolAddress((void**)&wqkvh, g_wqkvh);
    cudaGetSymbolAddress((void**)&wgh, g_wgh);
    cudaGetSymbolAddress((void**)&woh, g_woh);

    cudaFuncSetAttribute(gemm_hilo, cudaFuncAttributeMaxDynamicSharedMemorySize, GEMM_SMEM3);
    cudaFuncSetAttribute(gemm_hi, cudaFuncAttributeMaxDynamicSharedMemorySize, GEMM_SMEM2);
    cudaFuncSetAttribute(scan_gemm, cudaFuncAttributeMaxDynamicSharedMemorySize, GEMM_SMEM2);

    // fp16 prep: activations (hi+lo) + weights (hi only, transposed to [N,K])
    split4<<<(ROWS_ * HID_ / 4) / 256, 256>>>(hid, ah, al);
    tsplit1<<<dim3(KEYD / 32, HID_ / 32), 256>>>(Wq, wqkvh, HID_, KEYD);
    tsplit1<<<dim3(KEYD / 32, HID_ / 32), 256>>>(Wk, wqkvh + (size_t)KEYD * HID_, HID_, KEYD);
    tsplit1<<<dim3(VALD / 32, HID_ / 32), 256>>>(Wv, wqkvh + (size_t)2 * KEYD * HID_, HID_, VALD);
    tsplit1<<<dim3(VALD / 32, HID_ / 32), 256>>>(Wg, wgh, HID_, VALD);
    tsplit1<<<dim3(HID_ / 32, VALD / 32), 256>>>(Wo, woh, VALD, HID_);

    // beta / decay (before the fat kernel)
    transpose6<<<(H_ * HID_) / 256, 256>>>(Wa, Wb, wat, wbt);
    proj_ab<<<(ROWS_ * 32) / 256, 256>>>(hid, wat, wbt, Alog, dtb, gd, bt);

    // fused Q|K|V projection (N = 6144, 2-product split fp16, 3-way routed)
    gemm_hilo<<<dim3((2 * KEYD + VALD) / 128, ROWS_ / 128), 256, GEMM_SMEM3>>>(
        ah, al, wqkvh, xq, xk, xv, KEYD, 2 * KEYD, KEYD, KEYD, VALD, HID_);

    // fused conv + silu (q,k,v in one launch)
    conv_silu_all<<<(ROWS_ * (2 * KEYD + VALD)) / 256, 256>>>(
        xq, xk, xv, cwq, cwk, cwv, qn, kn, vn);

    // fused l2 norms (q scaled by 1/16, k unit)
    l2norm_qk<<<(2 * ROWS_ * H_ * 32) / 256, 256>>>(qn, kn);

    // fat kernel: scan on 96 CTAs + single-product gate GEMM backfilling idle SMs
    scan_gemm<<<SCAN_CTAS + (VALD / 128) * (ROWS_ / 128), 256, GEMM_SMEM2>>>(
        qn, kn, vn, gd, bt, od, ah, wgh, gt);

    // rmsnorm * weight * silu(gate) -> fp16 hi
    norm_gate<<<(ROWS_ * H_ * 32) / 256, 256>>>(od, gt, nw, yh);

    // output projection (single-product fp16) -> d_out
    gemm_hi<<<dim3(HID_ / 128, ROWS_ / 128), 256, GEMM_SMEM2>>>(
        yh, woh, (float*)d_out, HID_, VALD);
}

// round 14
// speedup vs baseline: 1.1354x; 1.0399x over previous
#include <cuda_runtime.h>
#include <cuda_fp16.h>
#include <math.h>
#include <stdint.h>

// ---------------- problem constants ----------------
#define B_ 2
#define T_ 4096
#define HID_ 2048
#define H_ 6
#define DKH 256
#define DVH 512
#define KEYD 1536
#define VALD 3072
#define ROWS_ (B_ * T_)          // 8192
#define DVS 64                   // dv slice per scan CTA
#define NSL 8                    // 512/64
#define TOKB 8                   // tokens staged per scan round
#define LOSCALE 2048.0f
#define INVLOSCALE (1.0f / 2048.0f)
#define SCAN_CTAS (B_ * H_ * NSL)   // 96

// ---------------- scratch (device globals; no allocation allowed) ----------------
__device__ float g_xq[ROWS_ * KEYD];
__device__ float g_xk[ROWS_ * KEYD];
__device__ float g_xv[ROWS_ * VALD];
__device__ float g_gt[ROWS_ * VALD];
__device__ float g_qn[ROWS_ * KEYD];
__device__ float g_kn[ROWS_ * KEYD];
__device__ float g_vn[ROWS_ * VALD];
__device__ float g_od[ROWS_ * VALD];
__device__ float g_gd[ROWS_ * H_];
__device__ float g_bt[ROWS_ * H_];
__device__ float g_wat[H_ * HID_];
__device__ float g_wbt[H_ * HID_];
// fp16 buffers (activation lo scaled by 2^11); weights hi-only
__device__ __half g_ah[ROWS_ * HID_];
__device__ __half g_al[ROWS_ * HID_];
__device__ __half g_yh[ROWS_ * VALD];
__device__ __half g_wqkvh[(2 * KEYD + VALD) * HID_];  // Wq | Wk | Wv rows, [N,K]
__device__ __half g_wgh[VALD * HID_];
__device__ __half g_woh[HID_ * VALD];

// ---------------- packed f32x2 helpers ----------------
__device__ __forceinline__ unsigned long long pk2(float x, float y) {
    unsigned long long r;
    asm("mov.b64 %0, {%1, %2};" : "=l"(r) : "f"(x), "f"(y));
    return r;
}
__device__ __forceinline__ float2 up2(unsigned long long v) {
    float2 r;
    asm("mov.b64 {%0, %1}, %2;" : "=f"(r.x), "=f"(r.y) : "l"(v));
    return r;
}
__device__ __forceinline__ unsigned long long fma2u(unsigned long long a, unsigned long long b, unsigned long long c) {
    unsigned long long d;
    asm("fma.rn.f32x2 %0, %1, %2, %3;" : "=l"(d) : "l"(a), "l"(b), "l"(c));
    return d;
}
__device__ __forceinline__ unsigned long long mul2u(unsigned long long a, unsigned long long b) {
    unsigned long long d;
    asm("mul.rn.f32x2 %0, %1, %2;" : "=l"(d) : "l"(a), "l"(b));
    return d;
}

// ---------------- mma.sync / ldmatrix / cp.async helpers ----------------
__device__ __forceinline__ uint32_t smem_u32(const void* p) {
    uint32_t a;
    asm("{ .reg .u64 t; cvta.to.shared.u64 t, %1; cvt.u32.u64 %0, t; }" : "=r"(a) : "l"(p));
    return a;
}
__device__ __forceinline__ void ldm_x4(uint32_t* r, uint32_t addr) {
    asm volatile("ldmatrix.sync.aligned.m8n8.x4.shared.b16 {%0,%1,%2,%3}, [%4];"
                 : "=r"(r[0]), "=r"(r[1]), "=r"(r[2]), "=r"(r[3]) : "r"(addr));
}
__device__ __forceinline__ void mma_hf32(float* c, const uint32_t* a, const uint32_t* b) {
    asm volatile("mma.sync.aligned.m16n8k16.row.col.f32.f16.f16.f32 "
                 "{%0,%1,%2,%3}, {%4,%5,%6,%7}, {%8,%9}, {%0,%1,%2,%3};"
                 : "+f"(c[0]), "+f"(c[1]), "+f"(c[2]), "+f"(c[3])
                 : "r"(a[0]), "r"(a[1]), "r"(a[2]), "r"(a[3]), "r"(b[0]), "r"(b[1]));
}
__device__ __forceinline__ void mma_hf16(uint32_t* c, const uint32_t* a, const uint32_t* b) {
    asm volatile("mma.sync.aligned.m16n8k16.row.col.f16.f16.f16.f16 "
                 "{%0,%1}, {%2,%3,%4,%5}, {%6,%7}, {%0,%1};"
                 : "+r"(c[0]), "+r"(c[1])
                 : "r"(a[0]), "r"(a[1]), "r"(a[2]), "r"(a[3]), "r"(b[0]), "r"(b[1]));
}
__device__ __forceinline__ void cp16(uint32_t sm, const void* gp) {
    asm volatile("cp.async.cg.shared.global [%0], [%1], 16;" :: "r"(sm), "l"(gp));
}
#define CP_COMMIT() asm volatile("cp.async.commit_group;" ::: "memory")
#define CP_WAIT0()  asm volatile("cp.async.wait_group 0;" ::: "memory")

// ---------------- fp16 HMMA GEMM tile, templated on precision ----------------
// USE_LO=true : C = Ah*Bh (f32 acc) + 2^-11*(Al'*Bh) (f16 acc), 3 smem tiles.
// USE_LO=false: C = Ah*Bh (f32 acc) only, 2 smem tiles (single-product fp16).
// CTA 128x128, 256 threads, warp tile 64x32, K-chunk 64, 2-stage cp.async (R8).
// SMEM rows padded to 72 halves (144B) -> conflict-free ldmatrix.
// 3-way column routing: [0,split1)->C0/str0, [split1,split2)->C1/str1, rest->C2/str2.
#define GTILE 18432            // 128 rows * 144 B
#define GEMM_SMEM3 110592      // 2 stages * 3 tiles
#define GEMM_SMEM2 73728       // 2 stages * 2 tiles

template <bool USE_LO>
__device__ __forceinline__ void gemm_tile(
    const __half* __restrict__ Ahi, const __half* __restrict__ Alo,
    const __half* __restrict__ Bhi,
    float* __restrict__ C0, float* __restrict__ C1, float* __restrict__ C2,
    int split1, int split2, int str0, int str1, int str2,
    int K, int bx, int by, char* smem) {
    constexpr int NT = USE_LO ? 3 : 2;        // tiles per stage (A[,Alo],B)
    constexpr int GBUF = NT * GTILE;
    const uint32_t sbase = smem_u32(smem);
    const int tid = threadIdx.x, lane = tid & 31, wid = tid >> 5;
    const int wm = wid & 1, wn = wid >> 1;    // 2 x 4 warp grid
    const int brow = by * 128, bcol = bx * 128;

    const __half* srcs[NT];
    int row0[NT];
    srcs[0] = Ahi; row0[0] = brow;
    if constexpr (USE_LO) { srcs[1] = Alo; row0[1] = brow; srcs[2] = Bhi; row0[2] = bcol; }
    else                  { srcs[1] = Bhi; row0[1] = bcol; }

    float accF[4][4][4];
    uint32_t accH[4][4][2];
#pragma unroll
    for (int i = 0; i < 4; i++)
#pragma unroll
        for (int j = 0; j < 4; j++) {
#pragma unroll
            for (int l = 0; l < 4; l++) accF[i][j][l] = 0.f;
            accH[i][j][0] = 0u; accH[i][j][1] = 0u;
        }

    const int r_ = tid >> 3, c8_ = (tid & 7) * 8;

    // prologue: chunk 0 -> buf 0
#pragma unroll
    for (int ts = 0; ts < NT; ts++) {
        const __half* sp = srcs[ts] + (size_t)(row0[ts] + r_) * K + c8_;
        uint32_t tb = sbase + ts * GTILE + r_ * 144 + c8_ * 2;
#pragma unroll
        for (int i = 0; i < 4; i++)
            cp16(tb + i * 32 * 144, sp + (size_t)(i * 32) * K);
    }
    CP_COMMIT();
    CP_WAIT0();
    __syncthreads();

    const int numT = K >> 6;
    const uint32_t a_lane = (lane & 15) * 144 + (lane >> 4) * 16;
    const uint32_t b_lane4 = ((lane & 7) + (lane >> 4) * 8) * 144 + ((lane >> 3) & 1) * 16;

    for (int c = 0; c < numT; c++) {
        const int b = c & 1;
        if (c + 1 < numT) {
            const int kc = (c + 1) << 6, nb = b ^ 1;
#pragma unroll
            for (int ts = 0; ts < NT; ts++) {
                const __half* sp = srcs[ts] + (size_t)(row0[ts] + r_) * K + kc + c8_;
                uint32_t tb = sbase + nb * GBUF + ts * GTILE + r_ * 144 + c8_ * 2;
#pragma unroll
                for (int i = 0; i < 4; i++)
                    cp16(tb + i * 32 * 144, sp + (size_t)(i * 32) * K);
            }
            CP_COMMIT();
        }
        const uint32_t aH = sbase + b * GBUF + wm * 64 * 144;
        const uint32_t aL = aH + GTILE;     // only valid if USE_LO
        const uint32_t bH = sbase + b * GBUF + (NT - 1) * GTILE + wn * 32 * 144;
#pragma unroll
        for (int ks = 0; ks < 4; ks++) {
            const uint32_t acol = ks * 32 + a_lane;
            const uint32_t bcol2 = ks * 32 + b_lane4;
            uint32_t fAH[4][4], fAL[4][4], fBH[4][2];
#pragma unroll
            for (int mt = 0; mt < 4; mt++) {
                ldm_x4(fAH[mt], aH + mt * 16 * 144 + acol);
                if constexpr (USE_LO) ldm_x4(fAL[mt], aL + mt * 16 * 144 + acol);
            }
#pragma unroll
            for (int p = 0; p < 2; p++) {
                uint32_t r4[4];
                ldm_x4(r4, bH + p * 16 * 144 + bcol2);
                fBH[2 * p][0] = r4[0]; fBH[2 * p][1] = r4[1];
                fBH[2 * p + 1][0] = r4[2]; fBH[2 * p + 1][1] = r4[3];
            }
#pragma unroll
            for (int mt = 0; mt < 4; mt++)
#pragma unroll
                for (int nt = 0; nt < 4; nt++) {
                    mma_hf32(accF[mt][nt], fAH[mt], fBH[nt]);
                    if constexpr (USE_LO) mma_hf16(accH[mt][nt], fAL[mt], fBH[nt]);
                }
        }
        CP_WAIT0();
        __syncthreads();
    }

    // epilogue: merge + 3-way route
    float* Cp; int ccol0, strN;
    if (bcol < split1)      { Cp = C0; ccol0 = bcol;          strN = str0; }
    else if (bcol < split2) { Cp = C1; ccol0 = bcol - split1; strN = str1; }
    else                    { Cp = C2; ccol0 = bcol - split2; strN = str2; }
    const int r0 = lane >> 2, cc = (lane & 3) * 2;
#pragma unroll
    for (int mt = 0; mt < 4; mt++)
#pragma unroll
        for (int nt = 0; nt < 4; nt++) {
            size_t base = (size_t)(brow + wm * 64 + mt * 16 + r0) * strN + ccol0 + wn * 32 + nt * 8 + cc;
            if constexpr (USE_LO) {
                float2 lo01 = __half22float2(*(__half2*)&accH[mt][nt][0]);
                float2 lo23 = __half22float2(*(__half2*)&accH[mt][nt][1]);
                *(float2*)&Cp[base] = make_float2(accF[mt][nt][0] + lo01.x * INVLOSCALE,
                                                  accF[mt][nt][1] + lo01.y * INVLOSCALE);
                *(float2*)&Cp[base + 8 * (size_t)strN] = make_float2(accF[mt][nt][2] + lo23.x * INVLOSCALE,
                                                                     accF[mt][nt][3] + lo23.y * INVLOSCALE);
            } else {
                *(float2*)&Cp[base] = make_float2(accF[mt][nt][0], accF[mt][nt][1]);
                *(float2*)&Cp[base + 8 * (size_t)strN] = make_float2(accF[mt][nt][2], accF[mt][nt][3]);
            }
        }
}

__global__ __launch_bounds__(256, 1)
void gemm_hilo(const __half* __restrict__ Ahi, const __half* __restrict__ Alo,
               const __half* __restrict__ Bhi,
               float* C0, float* C1, float* C2,
               int split1, int split2, int str0, int str1, int str2, int K) {
    extern __shared__ __align__(16) char smem[];
    gemm_tile<true>(Ahi, Alo, Bhi, C0, C1, C2, split1, split2, str0, str1, str2,
                    K, blockIdx.x, blockIdx.y, smem);
}

// single-product with full 3-way routing
__global__ __launch_bounds__(256, 1)
void gemm_hi3(const __half* __restrict__ Ahi, const __half* __restrict__ Bhi,
              float* C0, float* C1, float* C2,
              int split1, int split2, int str0, int str1, int str2, int K) {
    extern __shared__ __align__(16) char smem[];
    gemm_tile<false>(Ahi, Ahi, Bhi, C0, C1, C2, split1, split2, str0, str1, str2,
                     K, blockIdx.x, blockIdx.y, smem);
}

// ---------------- gated delta rule scan, device body (R8 known-good) ----------------
__device__ __forceinline__ void scan_body(
    const float* __restrict__ q, const float* __restrict__ k,
    const float* __restrict__ v, const float* __restrict__ g,
    const float* __restrict__ beta, float* __restrict__ o,
    int bi, char* smemc) {
    float (*ks)[272] = (float(*)[272])(smemc);
    float (*qs)[272] = (float(*)[272])(smemc + 8704);
    float (*vs)[DVS] = (float(*)[DVS])(smemc + 17408);
    float* egs = (float*)(smemc + 19456);
    float* bts = (float*)(smemc + 19488);

    const int s = bi & 7;
    const int h = (bi >> 3) % H_;
    const int b = bi / (H_ * NSL);
    const int tid = threadIdx.x;
    const int vl = tid >> 2, kseg = tid & 3;
    const int sidx = (tid >> 6) * 68 + (tid & 63);

    unsigned long long S[32];
#pragma unroll
    for (int m = 0; m < 32; m++) S[m] = 0ull;

    for (int t0 = 0; t0 < T_; t0 += TOKB) {
#pragma unroll
        for (int tt = 0; tt < TOKB; tt++) {
            size_t base = ((size_t)(b * T_ + t0 + tt) * H_ + h) * DKH;
            ks[tt][sidx] = k[base + tid];
            qs[tt][sidx] = q[base + tid];
        }
#pragma unroll
        for (int i = 0; i < 2; i++) {
            int ee = i * 256 + tid;
            int tt = ee >> 6, vle = ee & 63;
            vs[tt][vle] = v[((size_t)(b * T_ + t0 + tt) * H_ + h) * DVH + s * DVS + vle];
        }
        if (tid < TOKB) {
            size_t gi = (size_t)(b * T_ + t0 + tid) * H_ + h;
            egs[tid] = expf(g[gi]);
            bts[tid] = beta[gi];
        }
        __syncthreads();

#pragma unroll 1
        for (int tt = 0; tt < TOKB; tt++) {
            float eg = egs[tt], bt = bts[tt], vv = vs[tt][vl];
            const float4* kp = (const float4*)&ks[tt][kseg * 68];
            const float4* qp = (const float4*)&qs[tt][kseg * 68];

            unsigned long long a0 = 0ull, a1 = 0ull;
#pragma unroll
            for (int m4 = 0; m4 < 16; m4++) {
                float4 k4 = kp[m4];
                a0 = fma2u(pk2(k4.x, k4.y), S[2 * m4], a0);
                a1 = fma2u(pk2(k4.z, k4.w), S[2 * m4 + 1], a1);
            }
            float2 f0 = up2(a0), f1 = up2(a1);
            float pred = f0.x + f0.y + f1.x + f1.y;
            pred += __shfl_xor_sync(0xffffffffu, pred, 1);
            pred += __shfl_xor_sync(0xffffffffu, pred, 2);
            pred *= eg;
            float delta = (vv - pred) * bt;

            unsigned long long eg2 = pk2(eg, eg), d2 = pk2(delta, delta);
            unsigned long long o0 = 0ull, o1 = 0ull;
#pragma unroll
            for (int m4 = 0; m4 < 16; m4++) {
                float4 k4 = kp[m4];
                float4 q4 = qp[m4];
                unsigned long long s0 = fma2u(pk2(k4.x, k4.y), d2, mul2u(eg2, S[2 * m4]));
                unsigned long long s1 = fma2u(pk2(k4.z, k4.w), d2, mul2u(eg2, S[2 * m4 + 1]));
                S[2 * m4] = s0;
                S[2 * m4 + 1] = s1;
                o0 = fma2u(pk2(q4.x, q4.y), s0, o0);
                o1 = fma2u(pk2(q4.z, q4.w), s1, o1);
            }
            float2 g0 = up2(o0), g1 = up2(o1);
            float ov = g0.x + g0.y + g1.x + g1.y;
            ov += __shfl_xor_sync(0xffffffffu, ov, 1);
            ov += __shfl_xor_sync(0xffffffffu, ov, 2);
            if (kseg == 0)
                o[((size_t)(b * T_ + t0 + tt) * H_ + h) * DVH + s * DVS + vl] = ov;
        }
        __syncthreads();
    }
}

// ---------------- fat kernel: scan (96 CTAs) + single-product gate GEMM ----------------
__global__ __launch_bounds__(256, 1)
void scan_gemm(const float* __restrict__ qn, const float* __restrict__ kn,
               const float* __restrict__ vn, const float* __restrict__ gd,
               const float* __restrict__ bt, float* __restrict__ od,
               const __half* __restrict__ ah, const __half* __restrict__ wgh,
               float* __restrict__ gt) {
    extern __shared__ __align__(16) char smem[];
    if (blockIdx.x < SCAN_CTAS) {
        scan_body(qn, kn, vn, gd, bt, od, blockIdx.x, smem);
    } else {
        int gi = blockIdx.x - SCAN_CTAS;
        gemm_tile<false>(ah, ah, wgh, gt, gt, gt, VALD, VALD, VALD, VALD, VALD,
                         HID_, gi % (VALD / 128), gi / (VALD / 128), smem);
    }
}

// ---------------- fp32 -> fp16 hi/lo split (lo scaled by 2^11) ----------------
__global__ void split4(const float* __restrict__ x, __half* __restrict__ xh,
                       __half* __restrict__ xl) {
    int i4 = blockIdx.x * 256 + threadIdx.x;
    float4 v = ((const float4*)x)[i4];
    __half h0 = __float2half_rn(v.x), h1 = __float2half_rn(v.y);
    __half h2 = __float2half_rn(v.z), h3 = __float2half_rn(v.w);
    __half l0 = __float2half_rn((v.x - __half2float(h0)) * LOSCALE);
    __half l1 = __float2half_rn((v.y - __half2float(h1)) * LOSCALE);
    __half l2 = __float2half_rn((v.z - __half2float(h2)) * LOSCALE);
    __half l3 = __float2half_rn((v.w - __half2float(h3)) * LOSCALE);
    __half2* hp = (__half2*)(xh + (size_t)i4 * 4);
    __half2* lp = (__half2*)(xl + (size_t)i4 * 4);
    hp[0] = __halves2half2(h0, h1); hp[1] = __halves2half2(h2, h3);
    lp[0] = __halves2half2(l0, l1); lp[1] = __halves2half2(l2, l3);
}

// ---------------- weight transpose: W[K,N] -> Wh [N,K] fp16 (hi only) ----------------
__global__ void tsplit1(const float* __restrict__ W, __half* __restrict__ Wh, int K, int N) {
    __shared__ float tile[32][33];
    int n0 = blockIdx.x * 32, k0 = blockIdx.y * 32;
    int tx = threadIdx.x & 31, ty = threadIdx.x >> 5;   // 32x8
#pragma unroll
    for (int i = 0; i < 4; i++) {
        int k = k0 + ty + i * 8;
        tile[ty + i * 8][tx] = W[(size_t)k * N + n0 + tx];
    }
    __syncthreads();
#pragma unroll
    for (int i = 0; i < 4; i++) {
        int n = n0 + ty + i * 8;
        Wh[(size_t)n * K + k0 + tx] = __float2half_rn(tile[tx][ty + i * 8]);
    }
}

// ---------------- fused causal depthwise conv (K=4) + SiLU for q,k,v ----------------
__global__ void conv_silu_all(const float* __restrict__ xq, const float* __restrict__ xk,
                              const float* __restrict__ xv,
                              const float* __restrict__ wq, const float* __restrict__ wk,
                              const float* __restrict__ wv,
                              float* __restrict__ yq, float* __restrict__ yk,
                              float* __restrict__ yv) {
    int idx = blockIdx.x * 256 + threadIdx.x;
    const float* x; const float* w; float* y; int D;
    const int NQ = ROWS_ * KEYD;
    if (idx < NQ)           { x = xq; w = wq; y = yq; D = KEYD; }
    else if (idx < 2 * NQ)  { idx -= NQ; x = xk; w = wk; y = yk; D = KEYD; }
    else                    { idx -= 2 * NQ; x = xv; w = wv; y = yv; D = VALD; }
    int d = idx % D;
    int t = (idx / D) & (T_ - 1);
    float4 wvv = *(const float4*)(w + d * 4);
    float acc = x[idx] * wvv.w;
    if (t >= 1) acc += x[idx - D] * wvv.z;
    if (t >= 2) acc += x[idx - 2 * D] * wvv.y;
    if (t >= 3) acc += x[idx - 3 * D] * wvv.x;
    y[idx] = acc / (1.f + expf(-acc));
}

// ---------------- fused per-(b,t,h) L2 norm over 256 for q (x1/16) and k ----------------
__global__ void l2norm_qk(float* __restrict__ q, float* __restrict__ k) {
    int gw = (blockIdx.x * 256 + threadIdx.x) >> 5;
    int lane = threadIdx.x & 31;
    const int NR = ROWS_ * H_;
    float scale; float* x;
    if (gw < NR) { x = q; scale = 0.0625f; }
    else         { x = k; gw -= NR; scale = 1.0f; }
    float* row = x + (size_t)gw * DKH;
    float4 v0 = *(const float4*)(row + lane * 8);
    float4 v1 = *(const float4*)(row + lane * 8 + 4);
    float ss = v0.x * v0.x + v0.y * v0.y + v0.z * v0.z + v0.w * v0.w +
               v1.x * v1.x + v1.y * v1.y + v1.z * v1.z + v1.w * v1.w;
#pragma unroll
    for (int o = 16; o; o >>= 1) ss += __shfl_xor_sync(0xffffffffu, ss, o);
    float r = rsqrtf(ss) * scale;
    v0.x *= r; v0.y *= r; v0.z *= r; v0.w *= r;
    v1.x *= r; v1.y *= r; v1.z *= r; v1.w *= r;
    *(float4*)(row + lane * 8) = v0;
    *(float4*)(row + lane * 8 + 4) = v1;
}

// ---------------- transpose Wa/Wb (2048x6 -> 6x2048) ----------------
__global__ void transpose6(const float* __restrict__ Wa, const float* __restrict__ Wb,
                           float* __restrict__ WaT, float* __restrict__ WbT) {
    int i = blockIdx.x * 256 + threadIdx.x;
    int c = i / H_, h = i % H_;
    WaT[h * HID_ + c] = Wa[i];
    WbT[h * HID_ + c] = Wb[i];
}

// ---------------- beta / decay projection ----------------
__global__ void proj_ab(const float* __restrict__ hid, const float* __restrict__ WaT,
                        const float* __restrict__ WbT, const float* __restrict__ A_log,
                        const float* __restrict__ dt_bias,
                        float* __restrict__ gdec, float* __restrict__ beta) {
    int gw = (blockIdx.x * 256 + threadIdx.x) >> 5;
    int lane = threadIdx.x & 31;
    const float* hr = hid + (size_t)gw * HID_;
    float da0 = 0, da1 = 0, da2 = 0, da3 = 0, da4 = 0, da5 = 0;
    float db0 = 0, db1 = 0, db2 = 0, db3 = 0, db4 = 0, db5 = 0;
    for (int c = lane; c < HID_; c += 32) {
        float hv = hr[c];
        da0 += hv * WaT[0 * HID_ + c]; db0 += hv * WbT[0 * HID_ + c];
        da1 += hv * WaT[1 * HID_ + c]; db1 += hv * WbT[1 * HID_ + c];
        da2 += hv * WaT[2 * HID_ + c]; db2 += hv * WbT[2 * HID_ + c];
        da3 += hv * WaT[3 * HID_ + c]; db3 += hv * WbT[3 * HID_ + c];
        da4 += hv * WaT[4 * HID_ + c]; db4 += hv * WbT[4 * HID_ + c];
        da5 += hv * WaT[5 * HID_ + c]; db5 += hv * WbT[5 * HID_ + c];
    }
#pragma unroll
    for (int o = 16; o; o >>= 1) {
        da0 += __shfl_xor_sync(~0u, da0, o); db0 += __shfl_xor_sync(~0u, db0, o);
        da1 += __shfl_xor_sync(~0u, da1, o); db1 += __shfl_xor_sync(~0u, db1, o);
        da2 += __shfl_xor_sync(~0u, da2, o); db2 += __shfl_xor_sync(~0u, db2, o);
        da3 += __shfl_xor_sync(~0u, da3, o); db3 += __shfl_xor_sync(~0u, db3, o);
        da4 += __shfl_xor_sync(~0u, da4, o); db4 += __shfl_xor_sync(~0u, db4, o);
        da5 += __shfl_xor_sync(~0u, da5, o); db5 += __shfl_xor_sync(~0u, db5, o);
    }
    if (lane == 0) {
        float da[6] = {da0, da1, da2, da3, da4, da5};
        float db[6] = {db0, db1, db2, db3, db4, db5};
#pragma unroll
        for (int h = 0; h < 6; h++) {
            float x = da[h] + dt_bias[h];
            float sp = (x > 20.f) ? x : log1pf(expf(x));
            gdec[gw * H_ + h] = -expf(A_log[h]) * sp;
            beta[gw * H_ + h] = 1.f / (1.f + expf(-db[h]));
        }
    }
}

// ---------------- RMSNorm * weight * silu(gate) -> fp16 (hi only) ----------------
__global__ void norm_gate(const float* __restrict__ o, const float* __restrict__ gate,
                          const float* __restrict__ nw, __half* __restrict__ yh) {
    int gw = (blockIdx.x * 256 + threadIdx.x) >> 5;
    int lane = threadIdx.x & 31;
    size_t base = (size_t)gw * DVH;
    float4 v[4];
    float ss = 0.f;
#pragma unroll
    for (int i = 0; i < 4; i++) {
        v[i] = *(const float4*)(o + base + (lane + i * 32) * 4);
        ss += v[i].x * v[i].x + v[i].y * v[i].y + v[i].z * v[i].z + v[i].w * v[i].w;
    }
#pragma unroll
    for (int off = 16; off; off >>= 1) ss += __shfl_xor_sync(0xffffffffu, ss, off);
    float r = rsqrtf(ss * (1.f / 512.f) + 1e-5f);
#pragma unroll
    for (int i = 0; i < 4; i++) {
        int d4 = (lane + i * 32) * 4;
        float4 gt = *(const float4*)(gate + base + d4);
        float4 w = *(const float4*)(nw + d4);
        float o0 = v[i].x * r * w.x * (gt.x / (1.f + expf(-gt.x)));
        float o1 = v[i].y * r * w.y * (gt.y / (1.f + expf(-gt.y)));
        float o2 = v[i].z * r * w.z * (gt.z / (1.f + expf(-gt.z)));
        float o3 = v[i].w * r * w.w * (gt.w / (1.f + expf(-gt.w)));
        __half2* hp = (__half2*)(yh + base + d4);
        hp[0] = __halves2half2(__float2half_rn(o0), __float2half_rn(o1));
        hp[1] = __halves2half2(__float2half_rn(o2), __float2half_rn(o3));
    }
}

// ---------------- launch ----------------
extern "C" void kernel_launch(void* const* d_in, const int* in_sizes, int n_in,
                              void* d_out, int out_size) {
    const float* hid  = (const float*)d_in[0];
    const float* Wq   = (const float*)d_in[1];
    const float* Wk   = (const float*)d_in[2];
    const float* Wv   = (const float*)d_in[3];
    const float* Wa   = (const float*)d_in[4];
    const float* Wb   = (const float*)d_in[5];
    const float* Wg   = (const float*)d_in[6];
    const float* Wo   = (const float*)d_in[7];
    const float* cwq  = (const float*)d_in[8];
    const float* cwk  = (const float*)d_in[9];
    const float* cwv  = (const float*)d_in[10];
    const float* Alog = (const float*)d_in[11];
    const float* dtb  = (const float*)d_in[12];
    const float* nw   = (const float*)d_in[13];

    float *xq, *xk, *xv, *gt, *qn, *kn, *vn, *od, *gd, *bt, *wat, *wbt;
    __half *ah, *al, *yh, *wqkvh, *wgh, *woh;
    cudaGetSymbolAddress((void**)&xq, g_xq);
    cudaGetSymbolAddress((void**)&xk, g_xk);
    cudaGetSymbolAddress((void**)&xv, g_xv);
    cudaGetSymbolAddress((void**)&gt, g_gt);
    cudaGetSymbolAddress((void**)&qn, g_qn);
    cudaGetSymbolAddress((void**)&kn, g_kn);
    cudaGetSymbolAddress((void**)&vn, g_vn);
    cudaGetSymbolAddress((void**)&od, g_od);
    cudaGetSymbolAddress((void**)&gd, g_gd);
    cudaGetSymbolAddress((void**)&bt, g_bt);
    cudaGetSymbolAddress((void**)&wat, g_wat);
    cudaGetSymbolAddress((void**)&wbt, g_wbt);
    cudaGetSymbolAddress((void**)&ah, g_ah);
    cudaGetSymbolAddress((void**)&al, g_al);
    cudaGetSymbolAddress((void**)&yh, g_yh);
    cudaGetSymbolAddress((void**)&wqkvh, g_wqkvh);
    cudaGetSymbolAddress((void**)&wgh, g_wgh);
    cudaGetSymbolAddress((void**)&woh, g_woh);

    cudaFuncSetAttribute(gemm_hilo, cudaFuncAttributeMaxDynamicSharedMemorySize, GEMM_SMEM3);
    cudaFuncSetAttribute(gemm_hi3, cudaFuncAttributeMaxDynamicSharedMemorySize, GEMM_SMEM2);
    cudaFuncSetAttribute(scan_gemm, cudaFuncAttributeMaxDynamicSharedMemorySize, GEMM_SMEM2);

    // fp16 prep: activations (hi+lo) + weights (hi only, transposed to [N,K])
    split4<<<(ROWS_ * HID_ / 4) / 256, 256>>>(hid, ah, al);
    tsplit1<<<dim3(KEYD / 32, HID_ / 32), 256>>>(Wq, wqkvh, HID_, KEYD);
    tsplit1<<<dim3(KEYD / 32, HID_ / 32), 256>>>(Wk, wqkvh + (size_t)KEYD * HID_, HID_, KEYD);
    tsplit1<<<dim3(VALD / 32, HID_ / 32), 256>>>(Wv, wqkvh + (size_t)2 * KEYD * HID_, HID_, VALD);
    tsplit1<<<dim3(VALD / 32, HID_ / 32), 256>>>(Wg, wgh, HID_, VALD);
    tsplit1<<<dim3(HID_ / 32, VALD / 32), 256>>>(Wo, woh, VALD, HID_);

    // beta / decay (before the fat kernel)
    transpose6<<<(H_ * HID_) / 256, 256>>>(Wa, Wb, wat, wbt);
    proj_ab<<<(ROWS_ * 32) / 256, 256>>>(hid, wat, wbt, Alog, dtb, gd, bt);

    // Q|K projection: single-product (q,k are l2-normalized downstream), 2-way routed
    gemm_hi3<<<dim3(2 * KEYD / 128, ROWS_ / 128), 256, GEMM_SMEM2>>>(
        ah, wqkvh, xq, xk, xk, KEYD, 2 * KEYD, KEYD, KEYD, KEYD, HID_);

    // V projection: 2-product split fp16 (v enters recurrence raw)
    gemm_hilo<<<dim3(VALD / 128, ROWS_ / 128), 256, GEMM_SMEM3>>>(
        ah, al, wqkvh + (size_t)2 * KEYD * HID_, xv, xv, xv, VALD, VALD, VALD, VALD, VALD, HID_);

    // fused conv + silu (q,k,v in one launch)
    conv_silu_all<<<(ROWS_ * (2 * KEYD + VALD)) / 256, 256>>>(
        xq, xk, xv, cwq, cwk, cwv, qn, kn, vn);

    // fused l2 norms (q scaled by 1/16, k unit)
    l2norm_qk<<<(2 * ROWS_ * H_ * 32) / 256, 256>>>(qn, kn);

    // fat kernel: scan on 96 CTAs + single-product gate GEMM backfilling idle SMs
    scan_gemm<<<SCAN_CTAS + (VALD / 128) * (ROWS_ / 128), 256, GEMM_SMEM2>>>(
        qn, kn, vn, gd, bt, od, ah, wgh, gt);

    // rmsnorm * weight * silu(gate) -> fp16 hi
    norm_gate<<<(ROWS_ * H_ * 32) / 256, 256>>>(od, gt, nw, yh);

    // output projection (single-product fp16) -> d_out
    gemm_hi3<<<dim3(HID_ / 128, ROWS_ / 128), 256, GEMM_SMEM2>>>(
        yh, woh, (float*)d_out, (float*)d_out, (float*)d_out,
        HID_, HID_, HID_, HID_, HID_, VALD);
}

// round 15
// speedup vs baseline: 1.1999x; 1.0568x over previous
#include <cuda_runtime.h>
#include <cuda_fp16.h>
#include <math.h>
#include <stdint.h>

// ---------------- problem constants ----------------
#define B_ 2
#define T_ 4096
#define HID_ 2048
#define H_ 6
#define DKH 256
#define DVH 512
#define KEYD 1536
#define VALD 3072
#define ROWS_ (B_ * T_)          // 8192
#define DVS 64                   // dv slice per scan CTA
#define NSL 8                    // 512/64
#define TOKB 8                   // tokens staged per scan round
#define SCAN_CTAS (B_ * H_ * NSL)   // 96

// ---------------- scratch (device globals; no allocation allowed) ----------------
__device__ float g_xq[ROWS_ * KEYD];
__device__ float g_xk[ROWS_ * KEYD];
__device__ float g_xv[ROWS_ * VALD];
__device__ float g_gt[ROWS_ * VALD];
__device__ float g_qn[ROWS_ * KEYD];
__device__ float g_kn[ROWS_ * KEYD];
__device__ float g_vn[ROWS_ * VALD];
__device__ float g_od[ROWS_ * VALD];
__device__ float g_gd[ROWS_ * H_];
__device__ float g_bt[ROWS_ * H_];
__device__ float g_wat[H_ * HID_];
__device__ float g_wbt[H_ * HID_];
// fp16 buffers (hi only everywhere; all GEMMs single-product)
__device__ __half g_ah[ROWS_ * HID_];
__device__ __half g_yh[ROWS_ * VALD];
__device__ __half g_wqkvh[(2 * KEYD + VALD) * HID_];  // Wq | Wk | Wv rows, [N,K]
__device__ __half g_wgh[VALD * HID_];
__device__ __half g_woh[HID_ * VALD];

// ---------------- packed f32x2 helpers ----------------
__device__ __forceinline__ unsigned long long pk2(float x, float y) {
    unsigned long long r;
    asm("mov.b64 %0, {%1, %2};" : "=l"(r) : "f"(x), "f"(y));
    return r;
}
__device__ __forceinline__ float2 up2(unsigned long long v) {
    float2 r;
    asm("mov.b64 {%0, %1}, %2;" : "=f"(r.x), "=f"(r.y) : "l"(v));
    return r;
}
__device__ __forceinline__ unsigned long long fma2u(unsigned long long a, unsigned long long b, unsigned long long c) {
    unsigned long long d;
    asm("fma.rn.f32x2 %0, %1, %2, %3;" : "=l"(d) : "l"(a), "l"(b), "l"(c));
    return d;
}
__device__ __forceinline__ unsigned long long mul2u(unsigned long long a, unsigned long long b) {
    unsigned long long d;
    asm("mul.rn.f32x2 %0, %1, %2;" : "=l"(d) : "l"(a), "l"(b));
    return d;
}

// ---------------- mma.sync / ldmatrix / cp.async helpers ----------------
__device__ __forceinline__ uint32_t smem_u32(const void* p) {
    uint32_t a;
    asm("{ .reg .u64 t; cvta.to.shared.u64 t, %1; cvt.u32.u64 %0, t; }" : "=r"(a) : "l"(p));
    return a;
}
__device__ __forceinline__ void ldm_x4(uint32_t* r, uint32_t addr) {
    asm volatile("ldmatrix.sync.aligned.m8n8.x4.shared.b16 {%0,%1,%2,%3}, [%4];"
                 : "=r"(r[0]), "=r"(r[1]), "=r"(r[2]), "=r"(r[3]) : "r"(addr));
}
__device__ __forceinline__ void mma_hf32(float* c, const uint32_t* a, const uint32_t* b) {
    asm volatile("mma.sync.aligned.m16n8k16.row.col.f32.f16.f16.f32 "
                 "{%0,%1,%2,%3}, {%4,%5,%6,%7}, {%8,%9}, {%0,%1,%2,%3};"
                 : "+f"(c[0]), "+f"(c[1]), "+f"(c[2]), "+f"(c[3])
                 : "r"(a[0]), "r"(a[1]), "r"(a[2]), "r"(a[3]), "r"(b[0]), "r"(b[1]));
}
__device__ __forceinline__ void cp16(uint32_t sm, const void* gp) {
    asm volatile("cp.async.cg.shared.global [%0], [%1], 16;" :: "r"(sm), "l"(gp));
}
#define CP_COMMIT() asm volatile("cp.async.commit_group;" ::: "memory")
#define CP_WAIT0()  asm volatile("cp.async.wait_group 0;" ::: "memory")

// ---------------- single-product fp16 HMMA GEMM tile ----------------
// C = Ah*Bh (f32 acc); B stored [N,K] hi-only. CTA 128x128, 256 threads,
// warp tile 64x32, K-chunk 64, 2-stage cp.async. Rows padded to 144 B.
// 3-way column routing: [0,split1)->C0/str0, [split1,split2)->C1/str1, rest->C2/str2.
#define GTILE 18432            // 128 rows * 144 B
#define GBUF  36864            // 2 tiles (A,B)
#define GEMM_SMEM 73728        // 2 stages

__device__ __forceinline__ void gemm_tile(
    const __half* __restrict__ Ahi, const __half* __restrict__ Bhi,
    float* __restrict__ C0, float* __restrict__ C1, float* __restrict__ C2,
    int split1, int split2, int str0, int str1, int str2,
    int K, int bx, int by, char* smem) {
    const uint32_t sbase = smem_u32(smem);
    const int tid = threadIdx.x, lane = tid & 31, wid = tid >> 5;
    const int wm = wid & 1, wn = wid >> 1;    // 2 x 4 warp grid
    const int brow = by * 128, bcol = bx * 128;

    const __half* srcs[2] = {Ahi, Bhi};
    const int row0[2] = {brow, bcol};

    float accF[4][4][4];
#pragma unroll
    for (int i = 0; i < 4; i++)
#pragma unroll
        for (int j = 0; j < 4; j++)
#pragma unroll
            for (int l = 0; l < 4; l++) accF[i][j][l] = 0.f;

    const int r_ = tid >> 3, c8_ = (tid & 7) * 8;

    // prologue: chunk 0 -> buf 0
#pragma unroll
    for (int ts = 0; ts < 2; ts++) {
        const __half* sp = srcs[ts] + (size_t)(row0[ts] + r_) * K + c8_;
        uint32_t tb = sbase + ts * GTILE + r_ * 144 + c8_ * 2;
#pragma unroll
        for (int i = 0; i < 4; i++)
            cp16(tb + i * 32 * 144, sp + (size_t)(i * 32) * K);
    }
    CP_COMMIT();
    CP_WAIT0();
    __syncthreads();

    const int numT = K >> 6;
    const uint32_t a_lane = (lane & 15) * 144 + (lane >> 4) * 16;
    const uint32_t b_lane4 = ((lane & 7) + (lane >> 4) * 8) * 144 + ((lane >> 3) & 1) * 16;

    for (int c = 0; c < numT; c++) {
        const int b = c & 1;
        if (c + 1 < numT) {
            const int kc = (c + 1) << 6, nb = b ^ 1;
#pragma unroll
            for (int ts = 0; ts < 2; ts++) {
                const __half* sp = srcs[ts] + (size_t)(row0[ts] + r_) * K + kc + c8_;
                uint32_t tb = sbase + nb * GBUF + ts * GTILE + r_ * 144 + c8_ * 2;
#pragma unroll
                for (int i = 0; i < 4; i++)
                    cp16(tb + i * 32 * 144, sp + (size_t)(i * 32) * K);
            }
            CP_COMMIT();
        }
        const uint32_t aH = sbase + b * GBUF + wm * 64 * 144;
        const uint32_t bH = sbase + b * GBUF + GTILE + wn * 32 * 144;
#pragma unroll
        for (int ks = 0; ks < 4; ks++) {
            const uint32_t acol = ks * 32 + a_lane;
            const uint32_t bcol2 = ks * 32 + b_lane4;
            uint32_t fAH[4][4], fBH[4][2];
#pragma unroll
            for (int mt = 0; mt < 4; mt++)
                ldm_x4(fAH[mt], aH + mt * 16 * 144 + acol);
#pragma unroll
            for (int p = 0; p < 2; p++) {
                uint32_t r4[4];
                ldm_x4(r4, bH + p * 16 * 144 + bcol2);
                fBH[2 * p][0] = r4[0]; fBH[2 * p][1] = r4[1];
                fBH[2 * p + 1][0] = r4[2]; fBH[2 * p + 1][1] = r4[3];
            }
#pragma unroll
            for (int mt = 0; mt < 4; mt++)
#pragma unroll
                for (int nt = 0; nt < 4; nt++)
                    mma_hf32(accF[mt][nt], fAH[mt], fBH[nt]);
        }
        CP_WAIT0();
        __syncthreads();
    }

    // epilogue: 3-way route
    float* Cp; int ccol0, strN;
    if (bcol < split1)      { Cp = C0; ccol0 = bcol;          strN = str0; }
    else if (bcol < split2) { Cp = C1; ccol0 = bcol - split1; strN = str1; }
    else                    { Cp = C2; ccol0 = bcol - split2; strN = str2; }
    const int r0 = lane >> 2, cc = (lane & 3) * 2;
#pragma unroll
    for (int mt = 0; mt < 4; mt++)
#pragma unroll
        for (int nt = 0; nt < 4; nt++) {
            size_t base = (size_t)(brow + wm * 64 + mt * 16 + r0) * strN + ccol0 + wn * 32 + nt * 8 + cc;
            *(float2*)&Cp[base] = make_float2(accF[mt][nt][0], accF[mt][nt][1]);
            *(float2*)&Cp[base + 8 * (size_t)strN] = make_float2(accF[mt][nt][2], accF[mt][nt][3]);
        }
}

__global__ __launch_bounds__(256, 1)
void gemm_hi3(const __half* __restrict__ Ahi, const __half* __restrict__ Bhi,
              float* C0, float* C1, float* C2,
              int split1, int split2, int str0, int str1, int str2, int K) {
    extern __shared__ __align__(16) char smem[];
    gemm_tile(Ahi, Bhi, C0, C1, C2, split1, split2, str0, str1, str2,
              K, blockIdx.x, blockIdx.y, smem);
}

// ---------------- gated delta rule scan, device body (R8 known-good) ----------------
__device__ __forceinline__ void scan_body(
    const float* __restrict__ q, const float* __restrict__ k,
    const float* __restrict__ v, const float* __restrict__ g,
    const float* __restrict__ beta, float* __restrict__ o,
    int bi, char* smemc) {
    float (*ks)[272] = (float(*)[272])(smemc);
    float (*qs)[272] = (float(*)[272])(smemc + 8704);
    float (*vs)[DVS] = (float(*)[DVS])(smemc + 17408);
    float* egs = (float*)(smemc + 19456);
    float* bts = (float*)(smemc + 19488);

    const int s = bi & 7;
    const int h = (bi >> 3) % H_;
    const int b = bi / (H_ * NSL);
    const int tid = threadIdx.x;
    const int vl = tid >> 2, kseg = tid & 3;
    const int sidx = (tid >> 6) * 68 + (tid & 63);

    unsigned long long S[32];
#pragma unroll
    for (int m = 0; m < 32; m++) S[m] = 0ull;

    for (int t0 = 0; t0 < T_; t0 += TOKB) {
#pragma unroll
        for (int tt = 0; tt < TOKB; tt++) {
            size_t base = ((size_t)(b * T_ + t0 + tt) * H_ + h) * DKH;
            ks[tt][sidx] = k[base + tid];
            qs[tt][sidx] = q[base + tid];
        }
#pragma unroll
        for (int i = 0; i < 2; i++) {
            int ee = i * 256 + tid;
            int tt = ee >> 6, vle = ee & 63;
            vs[tt][vle] = v[((size_t)(b * T_ + t0 + tt) * H_ + h) * DVH + s * DVS + vle];
        }
        if (tid < TOKB) {
            size_t gi = (size_t)(b * T_ + t0 + tid) * H_ + h;
            egs[tid] = expf(g[gi]);
            bts[tid] = beta[gi];
        }
        __syncthreads();

#pragma unroll 1
        for (int tt = 0; tt < TOKB; tt++) {
            float eg = egs[tt], bt = bts[tt], vv = vs[tt][vl];
            const float4* kp = (const float4*)&ks[tt][kseg * 68];
            const float4* qp = (const float4*)&qs[tt][kseg * 68];

            unsigned long long a0 = 0ull, a1 = 0ull;
#pragma unroll
            for (int m4 = 0; m4 < 16; m4++) {
                float4 k4 = kp[m4];
                a0 = fma2u(pk2(k4.x, k4.y), S[2 * m4], a0);
                a1 = fma2u(pk2(k4.z, k4.w), S[2 * m4 + 1], a1);
            }
            float2 f0 = up2(a0), f1 = up2(a1);
            float pred = f0.x + f0.y + f1.x + f1.y;
            pred += __shfl_xor_sync(0xffffffffu, pred, 1);
            pred += __shfl_xor_sync(0xffffffffu, pred, 2);
            pred *= eg;
            float delta = (vv - pred) * bt;

            unsigned long long eg2 = pk2(eg, eg), d2 = pk2(delta, delta);
            unsigned long long o0 = 0ull, o1 = 0ull;
#pragma unroll
            for (int m4 = 0; m4 < 16; m4++) {
                float4 k4 = kp[m4];
                float4 q4 = qp[m4];
                unsigned long long s0 = fma2u(pk2(k4.x, k4.y), d2, mul2u(eg2, S[2 * m4]));
                unsigned long long s1 = fma2u(pk2(k4.z, k4.w), d2, mul2u(eg2, S[2 * m4 + 1]));
                S[2 * m4] = s0;
                S[2 * m4 + 1] = s1;
                o0 = fma2u(pk2(q4.x, q4.y), s0, o0);
                o1 = fma2u(pk2(q4.z, q4.w), s1, o1);
            }
            float2 g0 = up2(o0), g1 = up2(o1);
            float ov = g0.x + g0.y + g1.x + g1.y;
            ov += __shfl_xor_sync(0xffffffffu, ov, 1);
            ov += __shfl_xor_sync(0xffffffffu, ov, 2);
            if (kseg == 0)
                o[((size_t)(b * T_ + t0 + tt) * H_ + h) * DVH + s * DVS + vl] = ov;
        }
        __syncthreads();
    }
}

// ---------------- fat kernel: scan (96 CTAs) + single-product gate GEMM ----------------
__global__ __launch_bounds__(256, 1)
void scan_gemm(const float* __restrict__ qn, const float* __restrict__ kn,
               const float* __restrict__ vn, const float* __restrict__ gd,
               const float* __restrict__ bt, float* __restrict__ od,
               const __half* __restrict__ ah, const __half* __restrict__ wgh,
               float* __restrict__ gt) {
    extern __shared__ __align__(16) char smem[];
    if (blockIdx.x < SCAN_CTAS) {
        scan_body(qn, kn, vn, gd, bt, od, blockIdx.x, smem);
    } else {
        int gi = blockIdx.x - SCAN_CTAS;
        gemm_tile(ah, wgh, gt, gt, gt, VALD, VALD, VALD, VALD, VALD,
                  HID_, gi % (VALD / 128), gi / (VALD / 128), smem);
    }
}

// ---------------- fp32 -> fp16 (hi only, vectorized) ----------------
__global__ void cvt4(const float* __restrict__ x, __half* __restrict__ xh) {
    int i4 = blockIdx.x * 256 + threadIdx.x;
    float4 v = ((const float4*)x)[i4];
    __half2* hp = (__half2*)(xh + (size_t)i4 * 4);
    hp[0] = __halves2half2(__float2half_rn(v.x), __float2half_rn(v.y));
    hp[1] = __halves2half2(__float2half_rn(v.z), __float2half_rn(v.w));
}

// ---------------- weight transpose: W[K,N] -> Wh [N,K] fp16 (hi only) ----------------
__global__ void tsplit1(const float* __restrict__ W, __half* __restrict__ Wh, int K, int N) {
    __shared__ float tile[32][33];
    int n0 = blockIdx.x * 32, k0 = blockIdx.y * 32;
    int tx = threadIdx.x & 31, ty = threadIdx.x >> 5;   // 32x8
#pragma unroll
    for (int i = 0; i < 4; i++) {
        int k = k0 + ty + i * 8;
        tile[ty + i * 8][tx] = W[(size_t)k * N + n0 + tx];
    }
    __syncthreads();
#pragma unroll
    for (int i = 0; i < 4; i++) {
        int n = n0 + ty + i * 8;
        Wh[(size_t)n * K + k0 + tx] = __float2half_rn(tile[tx][ty + i * 8]);
    }
}

// ---------------- fused causal depthwise conv (K=4) + SiLU for q,k,v ----------------
__global__ void conv_silu_all(const float* __restrict__ xq, const float* __restrict__ xk,
                              const float* __restrict__ xv,
                              const float* __restrict__ wq, const float* __restrict__ wk,
                              const float* __restrict__ wv,
                              float* __restrict__ yq, float* __restrict__ yk,
                              float* __restrict__ yv) {
    int idx = blockIdx.x * 256 + threadIdx.x;
    const float* x; const float* w; float* y; int D;
    const int NQ = ROWS_ * KEYD;
    if (idx < NQ)           { x = xq; w = wq; y = yq; D = KEYD; }
    else if (idx < 2 * NQ)  { idx -= NQ; x = xk; w = wk; y = yk; D = KEYD; }
    else                    { idx -= 2 * NQ; x = xv; w = wv; y = yv; D = VALD; }
    int d = idx % D;
    int t = (idx / D) & (T_ - 1);
    float4 wvv = *(const float4*)(w + d * 4);
    float acc = x[idx] * wvv.w;
    if (t >= 1) acc += x[idx - D] * wvv.z;
    if (t >= 2) acc += x[idx - 2 * D] * wvv.y;
    if (t >= 3) acc += x[idx - 3 * D] * wvv.x;
    y[idx] = acc / (1.f + expf(-acc));
}

// ---------------- fused per-(b,t,h) L2 norm over 256 for q (x1/16) and k ----------------
__global__ void l2norm_qk(float* __restrict__ q, float* __restrict__ k) {
    int gw = (blockIdx.x * 256 + threadIdx.x) >> 5;
    int lane = threadIdx.x & 31;
    const int NR = ROWS_ * H_;
    float scale; float* x;
    if (gw < NR) { x = q; scale = 0.0625f; }
    else         { x = k; gw -= NR; scale = 1.0f; }
    float* row = x + (size_t)gw * DKH;
    float4 v0 = *(const float4*)(row + lane * 8);
    float4 v1 = *(const float4*)(row + lane * 8 + 4);
    float ss = v0.x * v0.x + v0.y * v0.y + v0.z * v0.z + v0.w * v0.w +
               v1.x * v1.x + v1.y * v1.y + v1.z * v1.z + v1.w * v1.w;
#pragma unroll
    for (int o = 16; o; o >>= 1) ss += __shfl_xor_sync(0xffffffffu, ss, o);
    float r = rsqrtf(ss) * scale;
    v0.x *= r; v0.y *= r; v0.z *= r; v0.w *= r;
    v1.x *= r; v1.y *= r; v1.z *= r; v1.w *= r;
    *(float4*)(row + lane * 8) = v0;
    *(float4*)(row + lane * 8 + 4) = v1;
}

// ---------------- transpose Wa/Wb (2048x6 -> 6x2048) ----------------
__global__ void transpose6(const float* __restrict__ Wa, const float* __restrict__ Wb,
                           float* __restrict__ WaT, float* __restrict__ WbT) {
    int i = blockIdx.x * 256 + threadIdx.x;
    int c = i / H_, h = i % H_;
    WaT[h * HID_ + c] = Wa[i];
    WbT[h * HID_ + c] = Wb[i];
}

// ---------------- beta / decay projection ----------------
__global__ void proj_ab(const float* __restrict__ hid, const float* __restrict__ WaT,
                        const float* __restrict__ WbT, const float* __restrict__ A_log,
                        const float* __restrict__ dt_bias,
                        float* __restrict__ gdec, float* __restrict__ beta) {
    int gw = (blockIdx.x * 256 + threadIdx.x) >> 5;
    int lane = threadIdx.x & 31;
    const float* hr = hid + (size_t)gw * HID_;
    float da0 = 0, da1 = 0, da2 = 0, da3 = 0, da4 = 0, da5 = 0;
    float db0 = 0, db1 = 0, db2 = 0, db3 = 0, db4 = 0, db5 = 0;
    for (int c = lane; c < HID_; c += 32) {
        float hv = hr[c];
        da0 += hv * WaT[0 * HID_ + c]; db0 += hv * WbT[0 * HID_ + c];
        da1 += hv * WaT[1 * HID_ + c]; db1 += hv * WbT[1 * HID_ + c];
        da2 += hv * WaT[2 * HID_ + c]; db2 += hv * WbT[2 * HID_ + c];
        da3 += hv * WaT[3 * HID_ + c]; db3 += hv * WbT[3 * HID_ + c];
        da4 += hv * WaT[4 * HID_ + c]; db4 += hv * WbT[4 * HID_ + c];
        da5 += hv * WaT[5 * HID_ + c]; db5 += hv * WbT[5 * HID_ + c];
    }
#pragma unroll
    for (int o = 16; o; o >>= 1) {
        da0 += __shfl_xor_sync(~0u, da0, o); db0 += __shfl_xor_sync(~0u, db0, o);
        da1 += __shfl_xor_sync(~0u, da1, o); db1 += __shfl_xor_sync(~0u, db1, o);
        da2 += __shfl_xor_sync(~0u, da2, o); db2 += __shfl_xor_sync(~0u, db2, o);
        da3 += __shfl_xor_sync(~0u, da3, o); db3 += __shfl_xor_sync(~0u, db3, o);
        da4 += __shfl_xor_sync(~0u, da4, o); db4 += __shfl_xor_sync(~0u, db4, o);
        da5 += __shfl_xor_sync(~0u, da5, o); db5 += __shfl_xor_sync(~0u, db5, o);
    }
    if (lane == 0) {
        float da[6] = {da0, da1, da2, da3, da4, da5};
        float db[6] = {db0, db1, db2, db3, db4, db5};
#pragma unroll
        for (int h = 0; h < 6; h++) {
            float x = da[h] + dt_bias[h];
            float sp = (x > 20.f) ? x : log1pf(expf(x));
            gdec[gw * H_ + h] = -expf(A_log[h]) * sp;
            beta[gw * H_ + h] = 1.f / (1.f + expf(-db[h]));
        }
    }
}

// ---------------- RMSNorm * weight * silu(gate) -> fp16 (hi only) ----------------
__global__ void norm_gate(const float* __restrict__ o, const float* __restrict__ gate,
                          const float* __restrict__ nw, __half* __restrict__ yh) {
    int gw = (blockIdx.x * 256 + threadIdx.x) >> 5;
    int lane = threadIdx.x & 31;
    size_t base = (size_t)gw * DVH;
    float4 v[4];
    float ss = 0.f;
#pragma unroll
    for (int i = 0; i < 4; i++) {
        v[i] = *(const float4*)(o + base + (lane + i * 32) * 4);
        ss += v[i].x * v[i].x + v[i].y * v[i].y + v[i].z * v[i].z + v[i].w * v[i].w;
    }
#pragma unroll
    for (int off = 16; off; off >>= 1) ss += __shfl_xor_sync(0xffffffffu, ss, off);
    float r = rsqrtf(ss * (1.f / 512.f) + 1e-5f);
#pragma unroll
    for (int i = 0; i < 4; i++) {
        int d4 = (lane + i * 32) * 4;
        float4 gt = *(const float4*)(gate + base + d4);
        float4 w = *(const float4*)(nw + d4);
        float o0 = v[i].x * r * w.x * (gt.x / (1.f + expf(-gt.x)));
        float o1 = v[i].y * r * w.y * (gt.y / (1.f + expf(-gt.y)));
        float o2 = v[i].z * r * w.z * (gt.z / (1.f + expf(-gt.z)));
        float o3 = v[i].w * r * w.w * (gt.w / (1.f + expf(-gt.w)));
        __half2* hp = (__half2*)(yh + base + d4);
        hp[0] = __halves2half2(__float2half_rn(o0), __float2half_rn(o1));
        hp[1] = __halves2half2(__float2half_rn(o2), __float2half_rn(o3));
    }
}

// ---------------- launch ----------------
extern "C" void kernel_launch(void* const* d_in, const int* in_sizes, int n_in,
                              void* d_out, int out_size) {
    const float* hid  = (const float*)d_in[0];
    const float* Wq   = (const float*)d_in[1];
    const float* Wk   = (const float*)d_in[2];
    const float* Wv   = (const float*)d_in[3];
    const float* Wa   = (const float*)d_in[4];
    const float* Wb   = (const float*)d_in[5];
    const float* Wg   = (const float*)d_in[6];
    const float* Wo   = (const float*)d_in[7];
    const float* cwq  = (const float*)d_in[8];
    const float* cwk  = (const float*)d_in[9];
    const float* cwv  = (const float*)d_in[10];
    const float* Alog = (const float*)d_in[11];
    const float* dtb  = (const float*)d_in[12];
    const float* nw   = (const float*)d_in[13];

    float *xq, *xk, *xv, *gt, *qn, *kn, *vn, *od, *gd, *bt, *wat, *wbt;
    __half *ah, *yh, *wqkvh, *wgh, *woh;
    cudaGetSymbolAddress((void**)&xq, g_xq);
    cudaGetSymbolAddress((void**)&xk, g_xk);
    cudaGetSymbolAddress((void**)&xv, g_xv);
    cudaGetSymbolAddress((void**)&gt, g_gt);
    cudaGetSymbolAddress((void**)&qn, g_qn);
    cudaGetSymbolAddress((void**)&kn, g_kn);
    cudaGetSymbolAddress((void**)&vn, g_vn);
    cudaGetSymbolAddress((void**)&od, g_od);
    cudaGetSymbolAddress((void**)&gd, g_gd);
    cudaGetSymbolAddress((void**)&bt, g_bt);
    cudaGetSymbolAddress((void**)&wat, g_wat);
    cudaGetSymbolAddress((void**)&wbt, g_wbt);
    cudaGetSymbolAddress((void**)&ah, g_ah);
    cudaGetSymbolAddress((void**)&yh, g_yh);
    cudaGetSymbolAddress((void**)&wqkvh, g_wqkvh);
    cudaGetSymbolAddress((void**)&wgh, g_wgh);
    cudaGetSymbolAddress((void**)&woh, g_woh);

    cudaFuncSetAttribute(gemm_hi3, cudaFuncAttributeMaxDynamicSharedMemorySize, GEMM_SMEM);
    cudaFuncSetAttribute(scan_gemm, cudaFuncAttributeMaxDynamicSharedMemorySize, GEMM_SMEM);

    // fp16 prep: activations (hi only) + weights (hi only, transposed to [N,K])
    cvt4<<<(ROWS_ * HID_ / 4) / 256, 256>>>(hid, ah);
    tsplit1<<<dim3(KEYD / 32, HID_ / 32), 256>>>(Wq, wqkvh, HID_, KEYD);
    tsplit1<<<dim3(KEYD / 32, HID_ / 32), 256>>>(Wk, wqkvh + (size_t)KEYD * HID_, HID_, KEYD);
    tsplit1<<<dim3(VALD / 32, HID_ / 32), 256>>>(Wv, wqkvh + (size_t)2 * KEYD * HID_, HID_, VALD);
    tsplit1<<<dim3(VALD / 32, HID_ / 32), 256>>>(Wg, wgh, HID_, VALD);
    tsplit1<<<dim3(HID_ / 32, VALD / 32), 256>>>(Wo, woh, VALD, HID_);

    // beta / decay (before the fat kernel)
    transpose6<<<(H_ * HID_) / 256, 256>>>(Wa, Wb, wat, wbt);
    proj_ab<<<(ROWS_ * 32) / 256, 256>>>(hid, wat, wbt, Alog, dtb, gd, bt);

    // fused Q|K|V projection (N = 6144, single-product fp16, 3-way routed)
    gemm_hi3<<<dim3((2 * KEYD + VALD) / 128, ROWS_ / 128), 256, GEMM_SMEM>>>(
        ah, wqkvh, xq, xk, xv, KEYD, 2 * KEYD, KEYD, KEYD, VALD, HID_);

    // fused conv + silu (q,k,v in one launch)
    conv_silu_all<<<(ROWS_ * (2 * KEYD + VALD)) / 256, 256>>>(
        xq, xk, xv, cwq, cwk, cwv, qn, kn, vn);

    // fused l2 norms (q scaled by 1/16, k unit)
    l2norm_qk<<<(2 * ROWS_ * H_ * 32) / 256, 256>>>(qn, kn);

    // fat kernel: scan on 96 CTAs + single-product gate GEMM backfilling idle SMs
    scan_gemm<<<SCAN_CTAS + (VALD / 128) * (ROWS_ / 128), 256, GEMM_SMEM>>>(
        qn, kn, vn, gd, bt, od, ah, wgh, gt);

    // rmsnorm * weight * silu(gate) -> fp16 hi
    norm_gate<<<(ROWS_ * H_ * 32) / 256, 256>>>(od, gt, nw, yh);

    // output projection (single-product fp16) -> d_out
    gemm_hi3<<<dim3(HID_ / 128, ROWS_ / 128), 256, GEMM_SMEM>>>(
        yh, woh, (float*)d_out, (float*)d_out, (float*)d_out,
        HID_, HID_, HID_, HID_, HID_, VALD);
}